// round 14
// baseline (speedup 1.0000x reference)
#include <cuda_runtime.h>
#include <math.h>

#define BATCH   128
#define NITEMS  8192
#define HID     256
#define LAT     64
#define LEN1    4096
#define LEN2    8192
#define NEMB    512
#define NQ      4
#define MROWS   524288
#define VQBLOCKS 2048

// ---------------- scratch ----------------
__device__ float g_bufA[268435456];
__device__ float g_bufB[268435456];
__device__ float g_res [33554432];
__device__ float g_zq  [33554432];
__device__ float g_dvec[BATCH * NITEMS];
__device__ float g_counts[NEMB];
__device__ float g_scal[2];
__device__ float g_bsums[VQBLOCKS];
__device__ unsigned int g_xmax[8];
__device__ float g_Cval[8][256];

// grid-accumulator MAC (R11 proven): 4 ops/MAC, error capture exact.
#define GMAC(A, E, W, X) do {                                     \
    float _t2 = __fmaf_rn((W), (X), (A));                         \
    float _d  = __fsub_rn(_t2, (A));                              \
    float _e  = __fmaf_rn((W), (X), -_d);                         \
    (E) = __fadd_rn((E), _e);                                     \
    (A) = _t2;                                                    \
} while (0)

__global__ void k_makeC(const float* __restrict__ wt, int CO, int CIK, int slot)
{
    int co = threadIdx.x;
    if (co >= CO) return;
    float l1 = 0.f;
    const float* w = wt + (size_t)co * CIK;
    for (int i = 0; i < CIK; i++) l1 += fabsf(w[i]);
    float xm = __uint_as_float(g_xmax[slot]);
    float B = l1 * xm;
    float C = 1.0f;
    if (B > 0.f) C = ldexpf(1.0f, ilogbf(B) + 3);
    g_Cval[slot][co] = C;
}

__device__ __forceinline__ void blockmax_commit(float m, int slot)
{
    for (int off = 16; off > 0; off >>= 1)
        m = fmaxf(m, __shfl_xor_sync(0xffffffffu, m, off));
    if ((threadIdx.x & 31) == 0)
        atomicMax(&g_xmax[slot], __float_as_uint(m));
}

// =================================================================
// encoder conv1 (fp64-exact, tiny) + fused output max (slot 0)
// =================================================================
__global__ void __launch_bounds__(128) k_enc_conv1(
    const int* __restrict__ uid, const float* __restrict__ mat,
    const float* __restrict__ w, const float* __restrict__ bias,
    float* __restrict__ out)
{
    __shared__ float s_in[258];
    __shared__ float s_w[HID * 4];
    const int b  = blockIdx.y;
    const int l0 = blockIdx.x * 128;
    const int tx = threadIdx.x;
    const float* row = mat + (size_t)uid[b] * NITEMS;
    for (int i = tx; i < 258; i += 128) {
        int g = 2 * l0 - 1 + i;
        s_in[i] = (g >= 0 && g < NITEMS) ? row[g] : 0.f;
    }
    for (int i = tx; i < HID * 4; i += 128) s_w[i] = w[i];
    __syncthreads();
    const double x0 = s_in[2 * tx + 0], x1 = s_in[2 * tx + 1];
    const double x2 = s_in[2 * tx + 2], x3 = s_in[2 * tx + 3];
    const int l = l0 + tx;
    float m = 0.f;
    for (int co = 0; co < HID; co++) {
        double a = 0.0;
        a = fma((double)s_w[co * 4 + 0], x0, a);
        a = fma((double)s_w[co * 4 + 1], x1, a);
        a = fma((double)s_w[co * 4 + 2], x2, a);
        a = fma((double)s_w[co * 4 + 3], x3, a);
        float v = fmaxf(__fadd_rn((float)a, bias[co]), 0.f);
        m = fmaxf(m, v);
        out[((size_t)b * HID + co) * LEN1 + l] = v;
    }
    blockmax_commit(m, 0);
}

// =================================================================
// encoder conv1d, grid-accumulator exact. Tile 64co x 128l, CIC=32,
// vectorized x loads (row pad -> 16B aligned). MAC order == R13.
// =================================================================
template <int K, bool RELU, bool ADDRES, int OUTSLOT>
__global__ void __launch_bounds__(256) k_convgrid(
    const float* __restrict__ in, const float* __restrict__ wt,
    const float* __restrict__ bias, const float* __restrict__ res,
    float* __restrict__ out, int CO, int CI, int L, int slot)
{
    constexpr int PAD = (K - 1) / 2;
    constexpr int LT = 128, COT = 64, CIC = 32;
    constexpr int LWD = LT + 2 * PAD;              // valid width
    constexpr int LW  = (K == 3) ? 132 : 128;      // padded row (16B align)
    __shared__ float s_in[CIC][LW];
    __shared__ float s_w[CIC][K][COT];

    const int b   = blockIdx.z;
    const int co0 = blockIdx.y * COT;
    const int l0  = blockIdx.x * LT;
    const int tid = threadIdx.x;
    const int lq = tid & 15, cq = tid >> 4;
    const int ls = lq * 8, cs = cq * 4;

    float Cc[4];
#pragma unroll
    for (int i = 0; i < 4; i++) Cc[i] = g_Cval[slot][co0 + cs + i];

    float A[4][8], E[4][8];
#pragma unroll
    for (int i = 0; i < 4; i++)
#pragma unroll
        for (int j = 0; j < 8; j++) { A[i][j] = Cc[i]; E[i][j] = 0.f; }

    for (int ci0 = 0; ci0 < CI; ci0 += CIC) {
        for (int idx = tid; idx < CIC * LWD; idx += 256) {
            int ci = idx / LWD, x = idx % LWD;
            int l = l0 - PAD + x;
            float v = 0.f;
            if (l >= 0 && l < L) v = in[((size_t)b * CI + ci0 + ci) * L + l];
            s_in[ci][x] = v;
        }
        for (int idx = tid; idx < CIC * K * COT; idx += 256) {
            int co = idx % COT;
            int k  = (idx / COT) % K;
            int ci = idx / (COT * K);
            s_w[ci][k][co] = wt[((size_t)(co0 + co) * CI + ci0 + ci) * K + k];
        }
        __syncthreads();
#pragma unroll 2
        for (int ci = 0; ci < CIC; ci++) {
            float x[12];
            {
                float4 v0 = *reinterpret_cast<const float4*>(&s_in[ci][ls]);
                float4 v1 = *reinterpret_cast<const float4*>(&s_in[ci][ls + 4]);
                x[0] = v0.x; x[1] = v0.y; x[2] = v0.z; x[3] = v0.w;
                x[4] = v1.x; x[5] = v1.y; x[6] = v1.z; x[7] = v1.w;
                if (K == 3) {
                    float4 v2 = *reinterpret_cast<const float4*>(&s_in[ci][ls + 8]);
                    x[8] = v2.x; x[9] = v2.y; x[10] = v2.z; x[11] = v2.w;
                }
            }
#pragma unroll
            for (int k = 0; k < K; k++) {
                float4 w4 = *reinterpret_cast<const float4*>(&s_w[ci][k][cs]);
                float wv[4] = {w4.x, w4.y, w4.z, w4.w};
#pragma unroll
                for (int i = 0; i < 4; i++)
#pragma unroll
                    for (int j = 0; j < 8; j++)
                        GMAC(A[i][j], E[i][j], wv[i], x[j + k]);
            }
        }
        __syncthreads();
    }
    float m = 0.f;
#pragma unroll
    for (int i = 0; i < 4; i++) {
        const int co = co0 + cs + i;
        const float bv = bias[co];
        const size_t o = ((size_t)b * CO + co) * L + l0 + ls;
        float v[8];
#pragma unroll
        for (int j = 0; j < 8; j++) {
            float hi = __fsub_rn(A[i][j], Cc[i]);       // exact
            v[j] = __fadd_rn(__fadd_rn(hi, E[i][j]), bv);
        }
        if (ADDRES) {
            float4 r0 = *reinterpret_cast<const float4*>(&res[o]);
            float4 r1 = *reinterpret_cast<const float4*>(&res[o + 4]);
            v[0] = __fadd_rn(v[0], r0.x); v[1] = __fadd_rn(v[1], r0.y);
            v[2] = __fadd_rn(v[2], r0.z); v[3] = __fadd_rn(v[3], r0.w);
            v[4] = __fadd_rn(v[4], r1.x); v[5] = __fadd_rn(v[5], r1.y);
            v[6] = __fadd_rn(v[6], r1.z); v[7] = __fadd_rn(v[7], r1.w);
        }
        if (RELU) {
#pragma unroll
            for (int j = 0; j < 8; j++) v[j] = fmaxf(v[j], 0.f);
        }
        if (OUTSLOT >= 0) {
#pragma unroll
            for (int j = 0; j < 8; j++) m = fmaxf(m, v[j]);
        }
        float4 o0 = {v[0], v[1], v[2], v[3]};
        float4 o1 = {v[4], v[5], v[6], v[7]};
        *reinterpret_cast<float4*>(&out[o])     = o0;
        *reinterpret_cast<float4*>(&out[o + 4]) = o1;
    }
    if (OUTSLOT >= 0) blockmax_commit(m, OUTSLOT);
}

// =================================================================
// decoder conv1d (fp32 scalar), CIC=32, vectorized x loads
// =================================================================
template <int K, bool RELU, bool ADDRES>
__global__ void __launch_bounds__(256) k_conv(
    const float* __restrict__ in, const float* __restrict__ wt,
    const float* __restrict__ bias, const float* __restrict__ res,
    float* __restrict__ out, int CO, int CI, int L)
{
    constexpr int PAD = (K - 1) / 2;
    constexpr int LT = 128, COT = 64, CIC = 32;
    constexpr int LWD = LT + 2 * PAD;
    constexpr int LW  = (K == 3) ? 132 : 128;
    __shared__ float s_in[CIC][LW];
    __shared__ float s_w[CIC][K][COT];

    const int b   = blockIdx.z;
    const int co0 = blockIdx.y * COT;
    const int l0  = blockIdx.x * LT;
    const int tid = threadIdx.x;
    const int lq = tid & 15, cq = tid >> 4;
    const int ls = lq * 8, cs = cq * 4;

    float acc[4][8];
#pragma unroll
    for (int i = 0; i < 4; i++)
#pragma unroll
        for (int j = 0; j < 8; j++) acc[i][j] = 0.f;

    for (int ci0 = 0; ci0 < CI; ci0 += CIC) {
        for (int idx = tid; idx < CIC * LWD; idx += 256) {
            int ci = idx / LWD, x = idx % LWD;
            int l = l0 - PAD + x;
            float v = 0.f;
            if (l >= 0 && l < L) v = in[((size_t)b * CI + ci0 + ci) * L + l];
            s_in[ci][x] = v;
        }
        for (int idx = tid; idx < CIC * K * COT; idx += 256) {
            int co = idx % COT;
            int k  = (idx / COT) % K;
            int ci = idx / (COT * K);
            s_w[ci][k][co] = wt[((size_t)(co0 + co) * CI + ci0 + ci) * K + k];
        }
        __syncthreads();
#pragma unroll 2
        for (int ci = 0; ci < CIC; ci++) {
            float x[12];
            {
                float4 v0 = *reinterpret_cast<const float4*>(&s_in[ci][ls]);
                float4 v1 = *reinterpret_cast<const float4*>(&s_in[ci][ls + 4]);
                x[0] = v0.x; x[1] = v0.y; x[2] = v0.z; x[3] = v0.w;
                x[4] = v1.x; x[5] = v1.y; x[6] = v1.z; x[7] = v1.w;
                if (K == 3) {
                    float4 v2 = *reinterpret_cast<const float4*>(&s_in[ci][ls + 8]);
                    x[8] = v2.x; x[9] = v2.y; x[10] = v2.z; x[11] = v2.w;
                }
            }
#pragma unroll
            for (int k = 0; k < K; k++) {
                float4 w4 = *reinterpret_cast<const float4*>(&s_w[ci][k][cs]);
                float wv[4] = {w4.x, w4.y, w4.z, w4.w};
#pragma unroll
                for (int i = 0; i < 4; i++)
#pragma unroll
                    for (int j = 0; j < 8; j++)
                        acc[i][j] = fmaf(wv[i], x[j + k], acc[i][j]);
            }
        }
        __syncthreads();
    }
#pragma unroll
    for (int i = 0; i < 4; i++) {
        const int co = co0 + cs + i;
        const float bv = bias[co];
        const size_t o = ((size_t)b * CO + co) * L + l0 + ls;
        float v[8];
#pragma unroll
        for (int j = 0; j < 8; j++) v[j] = __fadd_rn(acc[i][j], bv);
        if (ADDRES) {
            float4 r0 = *reinterpret_cast<const float4*>(&res[o]);
            float4 r1 = *reinterpret_cast<const float4*>(&res[o + 4]);
            v[0] = __fadd_rn(v[0], r0.x); v[1] = __fadd_rn(v[1], r0.y);
            v[2] = __fadd_rn(v[2], r0.z); v[3] = __fadd_rn(v[3], r0.w);
            v[4] = __fadd_rn(v[4], r1.x); v[5] = __fadd_rn(v[5], r1.y);
            v[6] = __fadd_rn(v[6], r1.z); v[7] = __fadd_rn(v[7], r1.w);
        }
        if (RELU) {
#pragma unroll
            for (int j = 0; j < 8; j++) v[j] = fmaxf(v[j], 0.f);
        }
        float4 o0 = {v[0], v[1], v[2], v[3]};
        float4 o1 = {v[4], v[5], v[6], v[7]};
        *reinterpret_cast<float4*>(&out[o])     = o0;
        *reinterpret_cast<float4*>(&out[o + 4]) = o1;
    }
}

// =================================================================
// VQ: single-pass fp32 screen + exact fp64 refine
// =================================================================
__global__ void __launch_bounds__(256) k_vq(
    const float* __restrict__ cb, float* __restrict__ resid,
    float* __restrict__ zq, float* __restrict__ counts,
    float* __restrict__ bsums)
{
    extern __shared__ float sm[];
    float* s_code = sm;
    float* s_cn   = sm + NEMB * LAT;
    const int tid = threadIdx.x;

    for (int idx = tid; idx < NEMB * LAT / 4; idx += 256)
        reinterpret_cast<float4*>(s_code)[idx] =
            reinterpret_cast<const float4*>(cb)[idx];
    __syncthreads();
    for (int e = tid; e < NEMB; e += 256) {
        const float* c = s_code + e * LAT;
        double s = 0.0;
#pragma unroll
        for (int j = 0; j < 64; j++) s = fma((double)c[j], (double)c[j], s);
        s_cn[e] = (float)s;
    }
    __syncthreads();

    const size_t m = (size_t)blockIdx.x * 256 + tid;
    float r[64];
    {
        const float4* g = reinterpret_cast<const float4*>(resid + m * 64);
        float4* rr = reinterpret_cast<float4*>(r);
#pragma unroll
        for (int t = 0; t < 16; t++) rr[t] = g[t];
    }
    double rn64 = 0.0;
#pragma unroll
    for (int j = 0; j < 64; j++) rn64 = fma((double)r[j], (double)r[j], rn64);
    const float rn = (float)rn64;

    float sabs = 0.f;
#pragma unroll
    for (int j = 0; j < 64; j++) sabs = __fadd_rn(sabs, fabsf(r[j]));

    const float margin = 4.8e-7f * rn + 6.4e-8f * sabs + 1e-8f;

    float best_ka = 3.4e38f;
    int   cand[16];
    int   nc = 0;
    bool  overflow = false;
    for (int e = 0; e < NEMB; e += 4) {
        const float4* c0 = reinterpret_cast<const float4*>(s_code + (e + 0) * LAT);
        const float4* c1 = reinterpret_cast<const float4*>(s_code + (e + 1) * LAT);
        const float4* c2 = reinterpret_cast<const float4*>(s_code + (e + 2) * LAT);
        const float4* c3 = reinterpret_cast<const float4*>(s_code + (e + 3) * LAT);
        float d0 = 0.f, d1 = 0.f, d2 = 0.f, d3 = 0.f;
#pragma unroll
        for (int t = 0; t < 16; t++) {
            float4 a0 = c0[t], a1 = c1[t], a2 = c2[t], a3 = c3[t];
            float x0 = r[t*4+0], x1 = r[t*4+1], x2 = r[t*4+2], x3 = r[t*4+3];
            d0 = fmaf(a0.x, x0, d0); d0 = fmaf(a0.y, x1, d0);
            d0 = fmaf(a0.z, x2, d0); d0 = fmaf(a0.w, x3, d0);
            d1 = fmaf(a1.x, x0, d1); d1 = fmaf(a1.y, x1, d1);
            d1 = fmaf(a1.z, x2, d1); d1 = fmaf(a1.w, x3, d1);
            d2 = fmaf(a2.x, x0, d2); d2 = fmaf(a2.y, x1, d2);
            d2 = fmaf(a2.z, x2, d2); d2 = fmaf(a2.w, x3, d2);
            d3 = fmaf(a3.x, x0, d3); d3 = fmaf(a3.y, x1, d3);
            d3 = fmaf(a3.z, x2, d3); d3 = fmaf(a3.w, x3, d3);
        }
        float ka[4];
        ka[0] = __fsub_rn(__fadd_rn(rn, s_cn[e + 0]), __fmul_rn(2.f, d0));
        ka[1] = __fsub_rn(__fadd_rn(rn, s_cn[e + 1]), __fmul_rn(2.f, d1));
        ka[2] = __fsub_rn(__fadd_rn(rn, s_cn[e + 2]), __fmul_rn(2.f, d2));
        ka[3] = __fsub_rn(__fadd_rn(rn, s_cn[e + 3]), __fmul_rn(2.f, d3));
#pragma unroll
        for (int i = 0; i < 4; i++) {
            if (ka[i] < best_ka) best_ka = ka[i];
            if (ka[i] <= best_ka + margin) {
                if (nc < 16) cand[nc++] = e + i;
                else overflow = true;
            }
        }
    }

    float best = 3.4e38f;
    int bi = 0;
    if (!overflow) {
        for (int ci = 0; ci < nc; ci++) {
            int e = cand[ci];
            const float* c = s_code + (size_t)e * LAT;
            double dd = 0.0;
#pragma unroll
            for (int j = 0; j < 64; j++)
                dd = fma((double)c[j], (double)r[j], dd);
            float dot = (float)dd;
            float dist = __fsub_rn(__fadd_rn(rn, s_cn[e]),
                                   __fmul_rn(2.f, dot));
            if (dist < best) { best = dist; bi = e; }
        }
    } else {
        for (int e = 0; e < NEMB; e++) {
            const float* c = s_code + (size_t)e * LAT;
            double dd = 0.0;
#pragma unroll
            for (int j = 0; j < 64; j++)
                dd = fma((double)c[j], (double)r[j], dd);
            float dot = (float)dd;
            float dist = __fsub_rn(__fadd_rn(rn, s_cn[e]),
                                   __fmul_rn(2.f, dot));
            if (dist < best) { best = dist; bi = e; }
        }
    }

    float sq = 0.f;
    {
        const float* c = s_code + bi * LAT;
        float4* rg = reinterpret_cast<float4*>(resid + m * 64);
        float4* zg = reinterpret_cast<float4*>(zq + m * 64);
#pragma unroll
        for (int t = 0; t < 16; t++) {
            float4 zv = zg[t];
            float q[4] = {c[t*4+0], c[t*4+1], c[t*4+2], c[t*4+3]};
            float rv[4] = {r[t*4+0], r[t*4+1], r[t*4+2], r[t*4+3]};
            float4 nr, nz;
            float o_r[4], o_z[4];
#pragma unroll
            for (int u = 0; u < 4; u++) {
                float d  = __fsub_rn(q[u], rv[u]);
                sq = __fadd_rn(sq, __fmul_rn(d, d));
                float qs = __fadd_rn(rv[u], d);
                o_r[u] = __fsub_rn(rv[u], qs);
                o_z[u] = __fadd_rn((&zv.x)[u], qs);
            }
            nr.x = o_r[0]; nr.y = o_r[1]; nr.z = o_r[2]; nr.w = o_r[3];
            nz.x = o_z[0]; nz.y = o_z[1]; nz.z = o_z[2]; nz.w = o_z[3];
            rg[t] = nr; zg[t] = nz;
        }
    }
    atomicAdd(&counts[bi], 1.f);

    __shared__ float red[256];
    red[tid] = sq;
    __syncthreads();
    for (int s = 128; s > 0; s >>= 1) {
        if (tid < s) red[tid] += red[tid + s];
        __syncthreads();
    }
    if (tid == 0) bsums[blockIdx.x] = red[0];
}

__global__ void k_perp(const float* __restrict__ bsums, float* __restrict__ counts,
                       float* __restrict__ scal)
{
    __shared__ float red[512];
    __shared__ float red2[512];
    const int t = threadIdx.x;
    float c = counts[t];
    float avg = c * (1.0f / (float)MROWS);
    red[t] = avg * logf(avg + 1e-10f);
    float s2 = 0.f;
    for (int i = t; i < VQBLOCKS; i += 512) s2 += bsums[i];
    red2[t] = s2;
    __syncthreads();
    for (int s = 256; s > 0; s >>= 1) {
        if (t < s) { red[t] += red[t + s]; red2[t] += red2[t + s]; }
        __syncthreads();
    }
    if (t == 0) {
        scal[1] += expf(-red[0]);
        scal[0] += red2[0];
    }
    counts[t] = 0.f;
}

// =================================================================
// decoder ConvTranspose1d(64->256, K=4, s2, p1) + relu (fp32 scalar)
// vectorized x loads (row pad 66->68)
// =================================================================
__global__ void __launch_bounds__(256) k_dect(
    const float* __restrict__ in, const float* __restrict__ wt,
    const float* __restrict__ bias, float* __restrict__ out)
{
    constexpr int OT = 128, COT = 64, CIC = 32;
    __shared__ float s_in[CIC][68];
    __shared__ float s_w[CIC][4][COT];
    const int b   = blockIdx.z;
    const int co0 = blockIdx.y * COT;
    const int o0  = blockIdx.x * OT;
    const int tid = threadIdx.x;
    const int lq = tid & 15, cq = tid >> 4;
    const int os = lq * 8, cs = cq * 4;
    const int lbase = o0 / 2 - 1;

    float acc[4][8];
#pragma unroll
    for (int i = 0; i < 4; i++)
#pragma unroll
        for (int j = 0; j < 8; j++) acc[i][j] = 0.f;

    for (int ci0 = 0; ci0 < LAT; ci0 += CIC) {
        for (int idx = tid; idx < CIC * 66; idx += 256) {
            int ci = idx / 66, x = idx % 66;
            int l = lbase + x;
            float v = 0.f;
            if (l >= 0 && l < LEN1) v = in[((size_t)b * LAT + ci0 + ci) * LEN1 + l];
            s_in[ci][x] = v;
        }
        for (int idx = tid; idx < CIC * 4 * COT; idx += 256) {
            int co = idx & 63;
            int k  = (idx >> 6) & 3;
            int ci = idx >> 8;
            s_w[ci][k][co] = wt[((size_t)(ci0 + ci) * HID + co0 + co) * 4 + k];
        }
        __syncthreads();
#pragma unroll 4
        for (int ci = 0; ci < CIC; ci++) {
            float x[8];
            {
                float4 v0 = *reinterpret_cast<const float4*>(&s_in[ci][(os >> 1)]);
                float4 v1 = *reinterpret_cast<const float4*>(&s_in[ci][(os >> 1) + 4]);
                x[0] = v0.x; x[1] = v0.y; x[2] = v0.z; x[3] = v0.w;
                x[4] = v1.x; x[5] = v1.y; x[6] = v1.z; x[7] = v1.w;
            }
            float4 W0 = *reinterpret_cast<const float4*>(&s_w[ci][0][cs]);
            float4 W1 = *reinterpret_cast<const float4*>(&s_w[ci][1][cs]);
            float4 W2 = *reinterpret_cast<const float4*>(&s_w[ci][2][cs]);
            float4 W3 = *reinterpret_cast<const float4*>(&s_w[ci][3][cs]);
            float wa[4][4] = {{W0.x, W0.y, W0.z, W0.w},
                              {W1.x, W1.y, W1.z, W1.w},
                              {W2.x, W2.y, W2.z, W2.w},
                              {W3.x, W3.y, W3.z, W3.w}};
#pragma unroll
            for (int jj = 0; jj < 4; jj++) {
                float xe0 = x[jj], xe1 = x[jj + 1], xo2 = x[jj + 2];
#pragma unroll
                for (int i = 0; i < 4; i++) {
                    acc[i][2 * jj]     = fmaf(wa[1][i], xe1, fmaf(wa[3][i], xe0, acc[i][2 * jj]));
                    acc[i][2 * jj + 1] = fmaf(wa[0][i], xo2, fmaf(wa[2][i], xe1, acc[i][2 * jj + 1]));
                }
            }
        }
        __syncthreads();
    }
#pragma unroll
    for (int i = 0; i < 4; i++) {
        const int co = co0 + cs + i;
        const float bv = bias[co];
        const size_t o = ((size_t)b * HID + co) * LEN2 + o0 + os;
        float v[8];
#pragma unroll
        for (int j = 0; j < 8; j++) v[j] = fmaxf(__fadd_rn(acc[i][j], bv), 0.f);
        float4 q0 = {v[0], v[1], v[2], v[3]};
        float4 q1 = {v[4], v[5], v[6], v[7]};
        *reinterpret_cast<float4*>(&out[o])     = q0;
        *reinterpret_cast<float4*>(&out[o + 4]) = q1;
    }
}

// =================================================================
// decoder ConvTranspose1d(256->1, K=3, s1, p1) (fp32)
// =================================================================
__global__ void __launch_bounds__(256) k_decfinal(
    const float* __restrict__ in, const float* __restrict__ wt,
    const float* __restrict__ bias, float* __restrict__ out)
{
    __shared__ float s_w[HID * 3];
    __shared__ float s_in[32][258];
    const int b  = blockIdx.y;
    const int o0 = blockIdx.x * 256;
    const int tx = threadIdx.x;
    for (int i = tx; i < HID * 3; i += 256) s_w[i] = wt[i];
    float acc = 0.f;
    for (int cc = 0; cc < HID; cc += 32) {
        __syncthreads();
        for (int idx = tx; idx < 32 * 258; idx += 256) {
            int ci = idx / 258, x = idx % 258;
            int l = o0 - 1 + x;
            s_in[ci][x] = (l >= 0 && l < LEN2)
                        ? in[((size_t)b * HID + cc + ci) * LEN2 + l] : 0.f;
        }
        __syncthreads();
#pragma unroll 8
        for (int ci = 0; ci < 32; ci++) {
            acc = fmaf(s_w[(cc + ci) * 3 + 0], s_in[ci][tx + 2], acc);
            acc = fmaf(s_w[(cc + ci) * 3 + 1], s_in[ci][tx + 1], acc);
            acc = fmaf(s_w[(cc + ci) * 3 + 2], s_in[ci][tx + 0], acc);
        }
    }
    out[(size_t)b * LEN2 + o0 + tx] = __fadd_rn(acc, bias[0]);
}

// =================================================================
// out projection (fp32 scalar)
// =================================================================
__global__ void __launch_bounds__(256) k_outproj(
    const float* __restrict__ dv, const float* __restrict__ W,
    const float* __restrict__ bias, float* __restrict__ out)
{
    constexpr int KC = 32;
    __shared__ float s_d[KC][136];
    __shared__ float s_w[KC][68];
    const int j0  = blockIdx.x * 64;
    const int tid = threadIdx.x;
    const int bq = tid & 15, jq = tid >> 4;
    const int bs = bq * 8, js = jq * 4;
    float acc[8][4];
#pragma unroll
    for (int i = 0; i < 8; i++)
#pragma unroll
        for (int j = 0; j < 4; j++) acc[i][j] = 0.f;

    for (int k0 = 0; k0 < NITEMS; k0 += KC) {
        for (int idx = tid; idx < KC * 128; idx += 256) {
            int bb = idx >> 5, k = idx & 31;
            s_d[k][bb] = dv[(size_t)bb * NITEMS + k0 + k];
        }
        for (int idx = tid; idx < KC * 64; idx += 256) {
            int j = idx >> 5, k = idx & 31;
            s_w[k][j] = W[(size_t)(j0 + j) * NITEMS + k0 + k];
        }
        __syncthreads();
#pragma unroll
        for (int k = 0; k < KC; k++) {
            float4 w4 = *reinterpret_cast<const float4*>(&s_w[k][js]);
            float xb[8];
            *reinterpret_cast<float4*>(&xb[0]) = *reinterpret_cast<const float4*>(&s_d[k][bs]);
            *reinterpret_cast<float4*>(&xb[4]) = *reinterpret_cast<const float4*>(&s_d[k][bs + 4]);
            float wv[4] = {w4.x, w4.y, w4.z, w4.w};
#pragma unroll
            for (int i = 0; i < 8; i++)
#pragma unroll
                for (int j = 0; j < 4; j++)
                    acc[i][j] = fmaf(xb[i], wv[j], acc[i][j]);
        }
        __syncthreads();
    }
#pragma unroll
    for (int i = 0; i < 8; i++) {
#pragma unroll
        for (int j = 0; j < 4; j++)
            out[(size_t)(bs + i) * NITEMS + j0 + js + j] =
                __fadd_rn(acc[i][j], bias[j0 + js + j]);
    }
}

__global__ void k_final(const float* __restrict__ scal, float* __restrict__ out, int out_size)
{
    if (out_size >= BATCH * NITEMS + 2) {
        out[BATCH * NITEMS + 0] = 1.25f * scal[0] * (1.0f / 33554432.0f);
        out[BATCH * NITEMS + 1] = scal[1] * 0.25f;
    }
}

// =================================================================
extern "C" void kernel_launch(void* const* d_in, const int* in_sizes, int n_in,
                              void* d_out, int out_size)
{
    const int*   uid  = (const int*)  d_in[0];
    const float* mat  = (const float*)d_in[1];
    const float* ecw  = (const float*)d_in[2];
    const float* ecb  = (const float*)d_in[3];
    const float* erw1 = (const float*)d_in[4];
    const float* erb1 = (const float*)d_in[5];
    const float* erw2 = (const float*)d_in[6];
    const float* erb2 = (const float*)d_in[7];
    const float* efw  = (const float*)d_in[8];
    const float* efb  = (const float*)d_in[9];
    const float* cbs  = (const float*)d_in[10];
    const float* dtw  = (const float*)d_in[11];
    const float* dtb  = (const float*)d_in[12];
    const float* drw1 = (const float*)d_in[13];
    const float* drb1 = (const float*)d_in[14];
    const float* drw2 = (const float*)d_in[15];
    const float* drb2 = (const float*)d_in[16];
    const float* dfw  = (const float*)d_in[17];
    const float* dfb  = (const float*)d_in[18];
    const float* opw  = (const float*)d_in[19];
    const float* opb  = (const float*)d_in[20];
    float* out = (float*)d_out;

    float *bufA, *bufB, *resid, *zq, *dvec, *counts, *scal, *bsums;
    unsigned int* xmax;
    cudaGetSymbolAddress((void**)&bufA,   g_bufA);
    cudaGetSymbolAddress((void**)&bufB,   g_bufB);
    cudaGetSymbolAddress((void**)&resid,  g_res);
    cudaGetSymbolAddress((void**)&zq,     g_zq);
    cudaGetSymbolAddress((void**)&dvec,   g_dvec);
    cudaGetSymbolAddress((void**)&counts, g_counts);
    cudaGetSymbolAddress((void**)&scal,   g_scal);
    cudaGetSymbolAddress((void**)&bsums,  g_bsums);
    cudaGetSymbolAddress((void**)&xmax,   g_xmax);

    const int vq_smem = (NEMB * LAT + NEMB) * (int)sizeof(float);
    cudaFuncSetAttribute(k_vq, cudaFuncAttributeMaxDynamicSharedMemorySize, vq_smem);

    cudaMemsetAsync(zq, 0, (size_t)33554432 * sizeof(float), 0);
    cudaMemsetAsync(scal, 0, 2 * sizeof(float), 0);
    cudaMemsetAsync(counts, 0, NEMB * sizeof(float), 0);
    cudaMemsetAsync(xmax, 0, 8 * sizeof(unsigned int), 0);

    // ---------------- encoder (grid-accumulator exact, fused max) -------
    k_enc_conv1<<<dim3(LEN1 / 128, BATCH), 128>>>(uid, mat, ecw, ecb, bufA);

    k_makeC<<<1, 256>>>(erw1, HID, HID * 3, 0);
    k_convgrid<3, true, false, 1><<<dim3(LEN1 / 128, HID / 64, BATCH), 256>>>(
        bufA, erw1, erb1, nullptr, bufB, HID, HID, LEN1, 0);

    k_makeC<<<1, 256>>>(erw2, HID, HID * 1, 1);
    k_convgrid<1, true, true, 2><<<dim3(LEN1 / 128, HID / 64, BATCH), 256>>>(
        bufB, erw2, erb2, bufA, bufA, HID, HID, LEN1, 1);

    k_makeC<<<1, 256>>>(erw1 + (size_t)HID * HID * 3, HID, HID * 3, 2);
    k_convgrid<3, true, false, 3><<<dim3(LEN1 / 128, HID / 64, BATCH), 256>>>(
        bufA, erw1 + (size_t)HID * HID * 3, erb1 + HID, nullptr, bufB,
        HID, HID, LEN1, 2);

    k_makeC<<<1, 256>>>(erw2 + (size_t)HID * HID, HID, HID * 1, 3);
    k_convgrid<1, true, true, 4><<<dim3(LEN1 / 128, HID / 64, BATCH), 256>>>(
        bufB, erw2 + (size_t)HID * HID, erb2 + HID, bufA, bufA,
        HID, HID, LEN1, 3);

    k_makeC<<<1, 256>>>(efw, LAT, HID * 3, 4);
    k_convgrid<3, false, false, -1><<<dim3(LEN1 / 128, LAT / 64, BATCH), 256>>>(
        bufA, efw, efb, nullptr, resid, LAT, HID, LEN1, 4);

    // ---------------- residual VQ ----------------
    for (int q = 0; q < NQ; q++) {
        k_vq<<<VQBLOCKS, 256, vq_smem>>>(cbs + (size_t)q * NEMB * LAT,
                                         resid, zq, counts, bsums);
        k_perp<<<1, 512>>>(bsums, counts, scal);
    }

    // ---------------- decoder (fp32 scalar) ----------------
    k_dect<<<dim3(LEN2 / 128, HID / 64, BATCH), 256>>>(zq, dtw, dtb, bufA);
    for (int i = 0; i < 2; i++) {
        k_conv<3, true, false><<<dim3(LEN2 / 128, HID / 64, BATCH), 256>>>(
            bufA, drw1 + (size_t)i * HID * HID * 3, drb1 + i * HID, nullptr, bufB,
            HID, HID, LEN2);
        k_conv<1, true, true><<<dim3(LEN2 / 128, HID / 64, BATCH), 256>>>(
            bufB, drw2 + (size_t)i * HID * HID, drb2 + i * HID, bufA, bufA,
            HID, HID, LEN2);
    }
    k_decfinal<<<dim3(LEN2 / 256, BATCH), 256>>>(bufA, dfw, dfb, dvec);

    // ---------------- output projection + scalars ----------------
    k_outproj<<<NITEMS / 64, 256>>>(dvec, opw, opb, out);
    k_final<<<1, 1>>>(scal, out, out_size);
}

// round 15
// speedup vs baseline: 1.0256x; 1.0256x over previous
#include <cuda_runtime.h>
#include <cuda_bf16.h>
#include <math.h>

#define BATCH   128
#define NITEMS  8192
#define HID     256
#define LAT     64
#define LEN1    4096
#define LEN2    8192
#define NEMB    512
#define NQ      4
#define MROWS   524288
#define VQBLOCKS 2048

// ---------------- scratch ----------------
__device__ float g_bufA[268435456];
__device__ float g_bufB[268435456];
__device__ float g_res [33554432];
__device__ float g_zq  [33554432];
__device__ float g_dvec[BATCH * NITEMS];
__device__ float g_counts[NEMB];
__device__ float g_scal[2];
__device__ float g_bsums[VQBLOCKS];
__device__ unsigned int g_xmax[8];
__device__ float g_Cval[8][256];

// grid-accumulator MAC (R11/R13 proven): 4 ops/MAC, exact error capture.
#define GMAC(A, E, W, X) do {                                     \
    float _t2 = __fmaf_rn((W), (X), (A));                         \
    float _d  = __fsub_rn(_t2, (A));                              \
    float _e  = __fmaf_rn((W), (X), -_d);                         \
    (E) = __fadd_rn((E), _e);                                     \
    (A) = _t2;                                                    \
} while (0)

__global__ void k_makeC(const float* __restrict__ wt, int CO, int CIK, int slot)
{
    int co = threadIdx.x;
    if (co >= CO) return;
    float l1 = 0.f;
    const float* w = wt + (size_t)co * CIK;
    for (int i = 0; i < CIK; i++) l1 += fabsf(w[i]);
    float xm = __uint_as_float(g_xmax[slot]);
    float B = l1 * xm;
    float C = 1.0f;
    if (B > 0.f) C = ldexpf(1.0f, ilogbf(B) + 3);
    g_Cval[slot][co] = C;
}

__device__ __forceinline__ void blockmax_commit(float m, int slot)
{
    for (int off = 16; off > 0; off >>= 1)
        m = fmaxf(m, __shfl_xor_sync(0xffffffffu, m, off));
    if ((threadIdx.x & 31) == 0)
        atomicMax(&g_xmax[slot], __float_as_uint(m));
}

// bf16 mma m16n8k16, D = A*B + D (fp32 accum)
__device__ __forceinline__ void mma16816(float* d, const unsigned* a,
                                         unsigned b0, unsigned b1)
{
    asm volatile(
        "mma.sync.aligned.m16n8k16.row.col.f32.bf16.bf16.f32 "
        "{%0,%1,%2,%3}, {%4,%5,%6,%7}, {%8,%9}, {%0,%1,%2,%3};\n"
        : "+f"(d[0]), "+f"(d[1]), "+f"(d[2]), "+f"(d[3])
        : "r"(a[0]), "r"(a[1]), "r"(a[2]), "r"(a[3]), "r"(b0), "r"(b1));
}

// =================================================================
// encoder conv1 (fp64-exact, tiny) + fused output max (slot 0)
// =================================================================
__global__ void __launch_bounds__(128) k_enc_conv1(
    const int* __restrict__ uid, const float* __restrict__ mat,
    const float* __restrict__ w, const float* __restrict__ bias,
    float* __restrict__ out)
{
    __shared__ float s_in[258];
    __shared__ float s_w[HID * 4];
    const int b  = blockIdx.y;
    const int l0 = blockIdx.x * 128;
    const int tx = threadIdx.x;
    const float* row = mat + (size_t)uid[b] * NITEMS;
    for (int i = tx; i < 258; i += 128) {
        int g = 2 * l0 - 1 + i;
        s_in[i] = (g >= 0 && g < NITEMS) ? row[g] : 0.f;
    }
    for (int i = tx; i < HID * 4; i += 128) s_w[i] = w[i];
    __syncthreads();
    const double x0 = s_in[2 * tx + 0], x1 = s_in[2 * tx + 1];
    const double x2 = s_in[2 * tx + 2], x3 = s_in[2 * tx + 3];
    const int l = l0 + tx;
    float m = 0.f;
    for (int co = 0; co < HID; co++) {
        double a = 0.0;
        a = fma((double)s_w[co * 4 + 0], x0, a);
        a = fma((double)s_w[co * 4 + 1], x1, a);
        a = fma((double)s_w[co * 4 + 2], x2, a);
        a = fma((double)s_w[co * 4 + 3], x3, a);
        float v = fmaxf(__fadd_rn((float)a, bias[co]), 0.f);
        m = fmaxf(m, v);
        out[((size_t)b * HID + co) * LEN1 + l] = v;
    }
    blockmax_commit(m, 0);
}

// =================================================================
// encoder conv1d, grid-accumulator exact (R13: 64co x 128l, CIC=16)
// =================================================================
template <int K, bool RELU, bool ADDRES, int OUTSLOT>
__global__ void __launch_bounds__(256) k_convgrid(
    const float* __restrict__ in, const float* __restrict__ wt,
    const float* __restrict__ bias, const float* __restrict__ res,
    float* __restrict__ out, int CO, int CI, int L, int slot)
{
    constexpr int PAD = (K - 1) / 2;
    constexpr int LT = 128, COT = 64, CIC = 16;
    constexpr int LW = LT + 2 * PAD;
    __shared__ float s_in[CIC][LW];
    __shared__ float s_w[CIC][K][COT];

    const int b   = blockIdx.z;
    const int co0 = blockIdx.y * COT;
    const int l0  = blockIdx.x * LT;
    const int tid = threadIdx.x;
    const int lq = tid & 15, cq = tid >> 4;
    const int ls = lq * 8, cs = cq * 4;

    float Cc[4];
#pragma unroll
    for (int i = 0; i < 4; i++) Cc[i] = g_Cval[slot][co0 + cs + i];

    float A[4][8], E[4][8];
#pragma unroll
    for (int i = 0; i < 4; i++)
#pragma unroll
        for (int j = 0; j < 8; j++) { A[i][j] = Cc[i]; E[i][j] = 0.f; }

    for (int ci0 = 0; ci0 < CI; ci0 += CIC) {
        for (int idx = tid; idx < CIC * LW; idx += 256) {
            int ci = idx / LW, x = idx % LW;
            int l = l0 - PAD + x;
            float v = 0.f;
            if (l >= 0 && l < L) v = in[((size_t)b * CI + ci0 + ci) * L + l];
            s_in[ci][x] = v;
        }
        for (int idx = tid; idx < CIC * K * COT; idx += 256) {
            int co = idx % COT;
            int k  = (idx / COT) % K;
            int ci = idx / (COT * K);
            s_w[ci][k][co] = wt[((size_t)(co0 + co) * CI + ci0 + ci) * K + k];
        }
        __syncthreads();
#pragma unroll 2
        for (int ci = 0; ci < CIC; ci++) {
            float x[8 + K - 1];
#pragma unroll
            for (int t = 0; t < 8 + K - 1; t++) x[t] = s_in[ci][ls + t];
#pragma unroll
            for (int k = 0; k < K; k++) {
                float4 w4 = *reinterpret_cast<const float4*>(&s_w[ci][k][cs]);
                float wv[4] = {w4.x, w4.y, w4.z, w4.w};
#pragma unroll
                for (int i = 0; i < 4; i++)
#pragma unroll
                    for (int j = 0; j < 8; j++)
                        GMAC(A[i][j], E[i][j], wv[i], x[j + k]);
            }
        }
        __syncthreads();
    }
    float m = 0.f;
#pragma unroll
    for (int i = 0; i < 4; i++) {
        const int co = co0 + cs + i;
        const float bv = bias[co];
        const size_t o = ((size_t)b * CO + co) * L + l0 + ls;
        float v[8];
#pragma unroll
        for (int j = 0; j < 8; j++) {
            float hi = __fsub_rn(A[i][j], Cc[i]);
            v[j] = __fadd_rn(__fadd_rn(hi, E[i][j]), bv);
        }
        if (ADDRES) {
            float4 r0 = *reinterpret_cast<const float4*>(&res[o]);
            float4 r1 = *reinterpret_cast<const float4*>(&res[o + 4]);
            v[0] = __fadd_rn(v[0], r0.x); v[1] = __fadd_rn(v[1], r0.y);
            v[2] = __fadd_rn(v[2], r0.z); v[3] = __fadd_rn(v[3], r0.w);
            v[4] = __fadd_rn(v[4], r1.x); v[5] = __fadd_rn(v[5], r1.y);
            v[6] = __fadd_rn(v[6], r1.z); v[7] = __fadd_rn(v[7], r1.w);
        }
        if (RELU) {
#pragma unroll
            for (int j = 0; j < 8; j++) v[j] = fmaxf(v[j], 0.f);
        }
        if (OUTSLOT >= 0) {
#pragma unroll
            for (int j = 0; j < 8; j++) m = fmaxf(m, v[j]);
        }
        float4 o0 = {v[0], v[1], v[2], v[3]};
        float4 o1 = {v[4], v[5], v[6], v[7]};
        *reinterpret_cast<float4*>(&out[o])     = o0;
        *reinterpret_cast<float4*>(&out[o + 4]) = o1;
    }
    if (OUTSLOT >= 0) blockmax_commit(m, OUTSLOT);
}

// =================================================================
// decoder conv1d via bf16-split tensor cores (3 MMAs per MAC-tile)
// Tile: 64co x 128l, 8 warps, each warp: m-tile (16co) x 8 n-tiles (8l)
// =================================================================
template <int K, bool RELU, bool ADDRES>
__global__ void __launch_bounds__(256) k_convTC(
    const float* __restrict__ in, const float* __restrict__ wt,
    const float* __restrict__ bias, const float* __restrict__ res,
    float* __restrict__ out, int CO, int CI, int L)
{
    constexpr int PAD = (K - 1) / 2;
    constexpr int LT = 128, COT = 64, CIC = 16;
    constexpr int LWD = LT + 2 * PAD;             // 130 (K=3) / 128 (K=1)
    __shared__ __nv_bfloat16 s_xh[LWD][16];
    __shared__ __nv_bfloat16 s_xl[LWD][16];
    __shared__ __nv_bfloat16 s_wh[K][COT][16];
    __shared__ __nv_bfloat16 s_wl[K][COT][16];

    const int b    = blockIdx.z;
    const int co0  = blockIdx.y * COT;
    const int l0   = blockIdx.x * LT;
    const int tid  = threadIdx.x;
    const int warp = tid >> 5, lane = tid & 31;
    const int g    = lane >> 2, t4 = lane & 3;
    const int mi   = warp & 3;                    // which 16-row co tile
    const int nb   = (warp >> 2) * 64;            // l-range base (0 or 64)

    float acc[8][4];
#pragma unroll
    for (int t = 0; t < 8; t++)
#pragma unroll
        for (int u = 0; u < 4; u++) acc[t][u] = 0.f;

    for (int ci0 = 0; ci0 < CI; ci0 += CIC) {
        for (int idx = tid; idx < CIC * LWD; idx += 256) {
            int pos = idx >> 4, ci = idx & 15;
            int l = l0 - PAD + pos;
            float f = 0.f;
            if (l >= 0 && l < L) f = in[((size_t)b * CI + ci0 + ci) * L + l];
            __nv_bfloat16 h = __float2bfloat16(f);
            s_xh[pos][ci] = h;
            s_xl[pos][ci] = __float2bfloat16(f - __bfloat162float(h));
        }
        for (int idx = tid; idx < CIC * K * COT; idx += 256) {
            int co = idx % COT;
            int k  = (idx / COT) % K;
            int ci = idx / (COT * K);
            float f = wt[((size_t)(co0 + co) * CI + ci0 + ci) * K + k];
            __nv_bfloat16 h = __float2bfloat16(f);
            s_wh[k][co][ci] = h;
            s_wl[k][co][ci] = __float2bfloat16(f - __bfloat162float(h));
        }
        __syncthreads();
#pragma unroll
        for (int k = 0; k < K; k++) {
            unsigned ah[4], al[4];
            const int r0 = mi * 16 + g;
            ah[0] = *reinterpret_cast<const unsigned*>(&s_wh[k][r0][t4 * 2]);
            ah[1] = *reinterpret_cast<const unsigned*>(&s_wh[k][r0 + 8][t4 * 2]);
            ah[2] = *reinterpret_cast<const unsigned*>(&s_wh[k][r0][t4 * 2 + 8]);
            ah[3] = *reinterpret_cast<const unsigned*>(&s_wh[k][r0 + 8][t4 * 2 + 8]);
            al[0] = *reinterpret_cast<const unsigned*>(&s_wl[k][r0][t4 * 2]);
            al[1] = *reinterpret_cast<const unsigned*>(&s_wl[k][r0 + 8][t4 * 2]);
            al[2] = *reinterpret_cast<const unsigned*>(&s_wl[k][r0][t4 * 2 + 8]);
            al[3] = *reinterpret_cast<const unsigned*>(&s_wl[k][r0 + 8][t4 * 2 + 8]);
#pragma unroll
            for (int t = 0; t < 8; t++) {
                int xr = nb + t * 8 + g + k;      // padded x row for col n=g
                unsigned bh0 = *reinterpret_cast<const unsigned*>(&s_xh[xr][t4 * 2]);
                unsigned bh1 = *reinterpret_cast<const unsigned*>(&s_xh[xr][t4 * 2 + 8]);
                unsigned bl0 = *reinterpret_cast<const unsigned*>(&s_xl[xr][t4 * 2]);
                unsigned bl1 = *reinterpret_cast<const unsigned*>(&s_xl[xr][t4 * 2 + 8]);
                mma16816(acc[t], ah, bh0, bh1);
                mma16816(acc[t], ah, bl0, bl1);
                mma16816(acc[t], al, bh0, bh1);
            }
        }
        __syncthreads();
    }

    // epilogue: rows co0+mi*16+g (+8), cols l0+nb+t*8+t4*2 (+1)
    const int row0 = co0 + mi * 16 + g;
    const int row1 = row0 + 8;
    const float bv0 = bias[row0], bv1 = bias[row1];
#pragma unroll
    for (int t = 0; t < 8; t++) {
        const int col = l0 + nb + t * 8 + t4 * 2;
        const size_t o00 = ((size_t)b * CO + row0) * L + col;
        const size_t o10 = ((size_t)b * CO + row1) * L + col;
        float v00 = acc[t][0] + bv0, v01 = acc[t][1] + bv0;
        float v10 = acc[t][2] + bv1, v11 = acc[t][3] + bv1;
        if (ADDRES) {
            v00 += res[o00]; v01 += res[o00 + 1];
            v10 += res[o10]; v11 += res[o10 + 1];
        }
        if (RELU) {
            v00 = fmaxf(v00, 0.f); v01 = fmaxf(v01, 0.f);
            v10 = fmaxf(v10, 0.f); v11 = fmaxf(v11, 0.f);
        }
        out[o00] = v00; out[o00 + 1] = v01;
        out[o10] = v10; out[o10 + 1] = v11;
    }
}

// =================================================================
// VQ: single-pass fp32 screen + exact fp64 refine
// =================================================================
__global__ void __launch_bounds__(256) k_vq(
    const float* __restrict__ cb, float* __restrict__ resid,
    float* __restrict__ zq, float* __restrict__ counts,
    float* __restrict__ bsums)
{
    extern __shared__ float sm[];
    float* s_code = sm;
    float* s_cn   = sm + NEMB * LAT;
    const int tid = threadIdx.x;

    for (int idx = tid; idx < NEMB * LAT / 4; idx += 256)
        reinterpret_cast<float4*>(s_code)[idx] =
            reinterpret_cast<const float4*>(cb)[idx];
    __syncthreads();
    for (int e = tid; e < NEMB; e += 256) {
        const float* c = s_code + e * LAT;
        double s = 0.0;
#pragma unroll
        for (int j = 0; j < 64; j++) s = fma((double)c[j], (double)c[j], s);
        s_cn[e] = (float)s;
    }
    __syncthreads();

    const size_t m = (size_t)blockIdx.x * 256 + tid;
    float r[64];
    {
        const float4* g = reinterpret_cast<const float4*>(resid + m * 64);
        float4* rr = reinterpret_cast<float4*>(r);
#pragma unroll
        for (int t = 0; t < 16; t++) rr[t] = g[t];
    }
    double rn64 = 0.0;
#pragma unroll
    for (int j = 0; j < 64; j++) rn64 = fma((double)r[j], (double)r[j], rn64);
    const float rn = (float)rn64;

    float sabs = 0.f;
#pragma unroll
    for (int j = 0; j < 64; j++) sabs = __fadd_rn(sabs, fabsf(r[j]));

    const float margin = 4.8e-7f * rn + 6.4e-8f * sabs + 1e-8f;

    float best_ka = 3.4e38f;
    int   cand[16];
    int   nc = 0;
    bool  overflow = false;
    for (int e = 0; e < NEMB; e += 4) {
        const float4* c0 = reinterpret_cast<const float4*>(s_code + (e + 0) * LAT);
        const float4* c1 = reinterpret_cast<const float4*>(s_code + (e + 1) * LAT);
        const float4* c2 = reinterpret_cast<const float4*>(s_code + (e + 2) * LAT);
        const float4* c3 = reinterpret_cast<const float4*>(s_code + (e + 3) * LAT);
        float d0 = 0.f, d1 = 0.f, d2 = 0.f, d3 = 0.f;
#pragma unroll
        for (int t = 0; t < 16; t++) {
            float4 a0 = c0[t], a1 = c1[t], a2 = c2[t], a3 = c3[t];
            float x0 = r[t*4+0], x1 = r[t*4+1], x2 = r[t*4+2], x3 = r[t*4+3];
            d0 = fmaf(a0.x, x0, d0); d0 = fmaf(a0.y, x1, d0);
            d0 = fmaf(a0.z, x2, d0); d0 = fmaf(a0.w, x3, d0);
            d1 = fmaf(a1.x, x0, d1); d1 = fmaf(a1.y, x1, d1);
            d1 = fmaf(a1.z, x2, d1); d1 = fmaf(a1.w, x3, d1);
            d2 = fmaf(a2.x, x0, d2); d2 = fmaf(a2.y, x1, d2);
            d2 = fmaf(a2.z, x2, d2); d2 = fmaf(a2.w, x3, d2);
            d3 = fmaf(a3.x, x0, d3); d3 = fmaf(a3.y, x1, d3);
            d3 = fmaf(a3.z, x2, d3); d3 = fmaf(a3.w, x3, d3);
        }
        float ka[4];
        ka[0] = __fsub_rn(__fadd_rn(rn, s_cn[e + 0]), __fmul_rn(2.f, d0));
        ka[1] = __fsub_rn(__fadd_rn(rn, s_cn[e + 1]), __fmul_rn(2.f, d1));
        ka[2] = __fsub_rn(__fadd_rn(rn, s_cn[e + 2]), __fmul_rn(2.f, d2));
        ka[3] = __fsub_rn(__fadd_rn(rn, s_cn[e + 3]), __fmul_rn(2.f, d3));
#pragma unroll
        for (int i = 0; i < 4; i++) {
            if (ka[i] < best_ka) best_ka = ka[i];
            if (ka[i] <= best_ka + margin) {
                if (nc < 16) cand[nc++] = e + i;
                else overflow = true;
            }
        }
    }

    float best = 3.4e38f;
    int bi = 0;
    if (!overflow) {
        for (int ci = 0; ci < nc; ci++) {
            int e = cand[ci];
            const float* c = s_code + (size_t)e * LAT;
            double dd = 0.0;
#pragma unroll
            for (int j = 0; j < 64; j++)
                dd = fma((double)c[j], (double)r[j], dd);
            float dot = (float)dd;
            float dist = __fsub_rn(__fadd_rn(rn, s_cn[e]),
                                   __fmul_rn(2.f, dot));
            if (dist < best) { best = dist; bi = e; }
        }
    } else {
        for (int e = 0; e < NEMB; e++) {
            const float* c = s_code + (size_t)e * LAT;
            double dd = 0.0;
#pragma unroll
            for (int j = 0; j < 64; j++)
                dd = fma((double)c[j], (double)r[j], dd);
            float dot = (float)dd;
            float dist = __fsub_rn(__fadd_rn(rn, s_cn[e]),
                                   __fmul_rn(2.f, dot));
            if (dist < best) { best = dist; bi = e; }
        }
    }

    float sq = 0.f;
    {
        const float* c = s_code + bi * LAT;
        float4* rg = reinterpret_cast<float4*>(resid + m * 64);
        float4* zg = reinterpret_cast<float4*>(zq + m * 64);
#pragma unroll
        for (int t = 0; t < 16; t++) {
            float4 zv = zg[t];
            float q[4] = {c[t*4+0], c[t*4+1], c[t*4+2], c[t*4+3]};
            float rv[4] = {r[t*4+0], r[t*4+1], r[t*4+2], r[t*4+3]};
            float4 nr, nz;
            float o_r[4], o_z[4];
#pragma unroll
            for (int u = 0; u < 4; u++) {
                float d  = __fsub_rn(q[u], rv[u]);
                sq = __fadd_rn(sq, __fmul_rn(d, d));
                float qs = __fadd_rn(rv[u], d);
                o_r[u] = __fsub_rn(rv[u], qs);
                o_z[u] = __fadd_rn((&zv.x)[u], qs);
            }
            nr.x = o_r[0]; nr.y = o_r[1]; nr.z = o_r[2]; nr.w = o_r[3];
            nz.x = o_z[0]; nz.y = o_z[1]; nz.z = o_z[2]; nz.w = o_z[3];
            rg[t] = nr; zg[t] = nz;
        }
    }
    atomicAdd(&counts[bi], 1.f);

    __shared__ float red[256];
    red[tid] = sq;
    __syncthreads();
    for (int s = 128; s > 0; s >>= 1) {
        if (tid < s) red[tid] += red[tid + s];
        __syncthreads();
    }
    if (tid == 0) bsums[blockIdx.x] = red[0];
}

__global__ void k_perp(const float* __restrict__ bsums, float* __restrict__ counts,
                       float* __restrict__ scal)
{
    __shared__ float red[512];
    __shared__ float red2[512];
    const int t = threadIdx.x;
    float c = counts[t];
    float avg = c * (1.0f / (float)MROWS);
    red[t] = avg * logf(avg + 1e-10f);
    float s2 = 0.f;
    for (int i = t; i < VQBLOCKS; i += 512) s2 += bsums[i];
    red2[t] = s2;
    __syncthreads();
    for (int s = 256; s > 0; s >>= 1) {
        if (t < s) { red[t] += red[t + s]; red2[t] += red2[t + s]; }
        __syncthreads();
    }
    if (t == 0) {
        scal[1] += expf(-red[0]);
        scal[0] += red2[0];
    }
    counts[t] = 0.f;
}

// =================================================================
// decoder ConvTranspose1d(64->256, K=4, s2, p1) + relu (fp32 scalar)
// =================================================================
__global__ void __launch_bounds__(256) k_dect(
    const float* __restrict__ in, const float* __restrict__ wt,
    const float* __restrict__ bias, float* __restrict__ out)
{
    constexpr int OT = 128, COT = 64, CIC = 32;
    __shared__ float s_in[CIC][66];
    __shared__ float s_w[CIC][4][COT];
    const int b   = blockIdx.z;
    const int co0 = blockIdx.y * COT;
    const int o0  = blockIdx.x * OT;
    const int tid = threadIdx.x;
    const int lq = tid & 15, cq = tid >> 4;
    const int os = lq * 8, cs = cq * 4;
    const int lbase = o0 / 2 - 1;

    float acc[4][8];
#pragma unroll
    for (int i = 0; i < 4; i++)
#pragma unroll
        for (int j = 0; j < 8; j++) acc[i][j] = 0.f;

    for (int ci0 = 0; ci0 < LAT; ci0 += CIC) {
        for (int idx = tid; idx < CIC * 66; idx += 256) {
            int ci = idx / 66, x = idx % 66;
            int l = lbase + x;
            float v = 0.f;
            if (l >= 0 && l < LEN1) v = in[((size_t)b * LAT + ci0 + ci) * LEN1 + l];
            s_in[ci][x] = v;
        }
        for (int idx = tid; idx < CIC * 4 * COT; idx += 256) {
            int co = idx & 63;
            int k  = (idx >> 6) & 3;
            int ci = idx >> 8;
            s_w[ci][k][co] = wt[((size_t)(ci0 + ci) * HID + co0 + co) * 4 + k];
        }
        __syncthreads();
#pragma unroll 4
        for (int ci = 0; ci < CIC; ci++) {
            float x[6];
#pragma unroll
            for (int t = 0; t < 6; t++) x[t] = s_in[ci][(os >> 1) + t];
            float4 W0 = *reinterpret_cast<const float4*>(&s_w[ci][0][cs]);
            float4 W1 = *reinterpret_cast<const float4*>(&s_w[ci][1][cs]);
            float4 W2 = *reinterpret_cast<const float4*>(&s_w[ci][2][cs]);
            float4 W3 = *reinterpret_cast<const float4*>(&s_w[ci][3][cs]);
            float wa[4][4] = {{W0.x, W0.y, W0.z, W0.w},
                              {W1.x, W1.y, W1.z, W1.w},
                              {W2.x, W2.y, W2.z, W2.w},
                              {W3.x, W3.y, W3.z, W3.w}};
#pragma unroll
            for (int jj = 0; jj < 4; jj++) {
                float xe0 = x[jj], xe1 = x[jj + 1], xo2 = x[jj + 2];
#pragma unroll
                for (int i = 0; i < 4; i++) {
                    acc[i][2 * jj]     = fmaf(wa[1][i], xe1, fmaf(wa[3][i], xe0, acc[i][2 * jj]));
                    acc[i][2 * jj + 1] = fmaf(wa[0][i], xo2, fmaf(wa[2][i], xe1, acc[i][2 * jj + 1]));
                }
            }
        }
        __syncthreads();
    }
#pragma unroll
    for (int i = 0; i < 4; i++) {
        const int co = co0 + cs + i;
        const float bv = bias[co];
        const size_t o = ((size_t)b * HID + co) * LEN2 + o0 + os;
        float v[8];
#pragma unroll
        for (int j = 0; j < 8; j++) v[j] = fmaxf(__fadd_rn(acc[i][j], bv), 0.f);
        float4 q0 = {v[0], v[1], v[2], v[3]};
        float4 q1 = {v[4], v[5], v[6], v[7]};
        *reinterpret_cast<float4*>(&out[o])     = q0;
        *reinterpret_cast<float4*>(&out[o + 4]) = q1;
    }
}

// =================================================================
// decoder ConvTranspose1d(256->1, K=3, s1, p1) (fp32)
// =================================================================
__global__ void __launch_bounds__(256) k_decfinal(
    const float* __restrict__ in, const float* __restrict__ wt,
    const float* __restrict__ bias, float* __restrict__ out)
{
    __shared__ float s_w[HID * 3];
    __shared__ float s_in[32][258];
    const int b  = blockIdx.y;
    const int o0 = blockIdx.x * 256;
    const int tx = threadIdx.x;
    for (int i = tx; i < HID * 3; i += 256) s_w[i] = wt[i];
    float acc = 0.f;
    for (int cc = 0; cc < HID; cc += 32) {
        __syncthreads();
        for (int idx = tx; idx < 32 * 258; idx += 256) {
            int ci = idx / 258, x = idx % 258;
            int l = o0 - 1 + x;
            s_in[ci][x] = (l >= 0 && l < LEN2)
                        ? in[((size_t)b * HID + cc + ci) * LEN2 + l] : 0.f;
        }
        __syncthreads();
#pragma unroll 8
        for (int ci = 0; ci < 32; ci++) {
            acc = fmaf(s_w[(cc + ci) * 3 + 0], s_in[ci][tx + 2], acc);
            acc = fmaf(s_w[(cc + ci) * 3 + 1], s_in[ci][tx + 1], acc);
            acc = fmaf(s_w[(cc + ci) * 3 + 2], s_in[ci][tx + 0], acc);
        }
    }
    out[(size_t)b * LEN2 + o0 + tx] = __fadd_rn(acc, bias[0]);
}

// =================================================================
// out projection (fp32 scalar)
// =================================================================
__global__ void __launch_bounds__(256) k_outproj(
    const float* __restrict__ dv, const float* __restrict__ W,
    const float* __restrict__ bias, float* __restrict__ out)
{
    constexpr int KC = 32;
    __shared__ float s_d[KC][136];
    __shared__ float s_w[KC][68];
    const int j0  = blockIdx.x * 64;
    const int tid = threadIdx.x;
    const int bq = tid & 15, jq = tid >> 4;
    const int bs = bq * 8, js = jq * 4;
    float acc[8][4];
#pragma unroll
    for (int i = 0; i < 8; i++)
#pragma unroll
        for (int j = 0; j < 4; j++) acc[i][j] = 0.f;

    for (int k0 = 0; k0 < NITEMS; k0 += KC) {
        for (int idx = tid; idx < KC * 128; idx += 256) {
            int bb = idx >> 5, k = idx & 31;
            s_d[k][bb] = dv[(size_t)bb * NITEMS + k0 + k];
        }
        for (int idx = tid; idx < KC * 64; idx += 256) {
            int j = idx >> 5, k = idx & 31;
            s_w[k][j] = W[(size_t)(j0 + j) * NITEMS + k0 + k];
        }
        __syncthreads();
#pragma unroll
        for (int k = 0; k < KC; k++) {
            float4 w4 = *reinterpret_cast<const float4*>(&s_w[k][js]);
            float xb[8];
            *reinterpret_cast<float4*>(&xb[0]) = *reinterpret_cast<const float4*>(&s_d[k][bs]);
            *reinterpret_cast<float4*>(&xb[4]) = *reinterpret_cast<const float4*>(&s_d[k][bs + 4]);
            float wv[4] = {w4.x, w4.y, w4.z, w4.w};
#pragma unroll
            for (int i = 0; i < 8; i++)
#pragma unroll
                for (int j = 0; j < 4; j++)
                    acc[i][j] = fmaf(xb[i], wv[j], acc[i][j]);
        }
        __syncthreads();
    }
#pragma unroll
    for (int i = 0; i < 8; i++) {
#pragma unroll
        for (int j = 0; j < 4; j++)
            out[(size_t)(bs + i) * NITEMS + j0 + js + j] =
                __fadd_rn(acc[i][j], bias[j0 + js + j]);
    }
}

__global__ void k_final(const float* __restrict__ scal, float* __restrict__ out, int out_size)
{
    if (out_size >= BATCH * NITEMS + 2) {
        out[BATCH * NITEMS + 0] = 1.25f * scal[0] * (1.0f / 33554432.0f);
        out[BATCH * NITEMS + 1] = scal[1] * 0.25f;
    }
}

// =================================================================
extern "C" void kernel_launch(void* const* d_in, const int* in_sizes, int n_in,
                              void* d_out, int out_size)
{
    const int*   uid  = (const int*)  d_in[0];
    const float* mat  = (const float*)d_in[1];
    const float* ecw  = (const float*)d_in[2];
    const float* ecb  = (const float*)d_in[3];
    const float* erw1 = (const float*)d_in[4];
    const float* erb1 = (const float*)d_in[5];
    const float* erw2 = (const float*)d_in[6];
    const float* erb2 = (const float*)d_in[7];
    const float* efw  = (const float*)d_in[8];
    const float* efb  = (const float*)d_in[9];
    const float* cbs  = (const float*)d_in[10];
    const float* dtw  = (const float*)d_in[11];
    const float* dtb  = (const float*)d_in[12];
    const float* drw1 = (const float*)d_in[13];
    const float* drb1 = (const float*)d_in[14];
    const float* drw2 = (const float*)d_in[15];
    const float* drb2 = (const float*)d_in[16];
    const float* dfw  = (const float*)d_in[17];
    const float* dfb  = (const float*)d_in[18];
    const float* opw  = (const float*)d_in[19];
    const float* opb  = (const float*)d_in[20];
    float* out = (float*)d_out;

    float *bufA, *bufB, *resid, *zq, *dvec, *counts, *scal, *bsums;
    unsigned int* xmax;
    cudaGetSymbolAddress((void**)&bufA,   g_bufA);
    cudaGetSymbolAddress((void**)&bufB,   g_bufB);
    cudaGetSymbolAddress((void**)&resid,  g_res);
    cudaGetSymbolAddress((void**)&zq,     g_zq);
    cudaGetSymbolAddress((void**)&dvec,   g_dvec);
    cudaGetSymbolAddress((void**)&counts, g_counts);
    cudaGetSymbolAddress((void**)&scal,   g_scal);
    cudaGetSymbolAddress((void**)&bsums,  g_bsums);
    cudaGetSymbolAddress((void**)&xmax,   g_xmax);

    const int vq_smem = (NEMB * LAT + NEMB) * (int)sizeof(float);
    cudaFuncSetAttribute(k_vq, cudaFuncAttributeMaxDynamicSharedMemorySize, vq_smem);

    cudaMemsetAsync(zq, 0, (size_t)33554432 * sizeof(float), 0);
    cudaMemsetAsync(scal, 0, 2 * sizeof(float), 0);
    cudaMemsetAsync(counts, 0, NEMB * sizeof(float), 0);
    cudaMemsetAsync(xmax, 0, 8 * sizeof(unsigned int), 0);

    // ---------------- encoder (grid-accumulator exact, fused max) -------
    k_enc_conv1<<<dim3(LEN1 / 128, BATCH), 128>>>(uid, mat, ecw, ecb, bufA);

    k_makeC<<<1, 256>>>(erw1, HID, HID * 3, 0);
    k_convgrid<3, true, false, 1><<<dim3(LEN1 / 128, HID / 64, BATCH), 256>>>(
        bufA, erw1, erb1, nullptr, bufB, HID, HID, LEN1, 0);

    k_makeC<<<1, 256>>>(erw2, HID, HID * 1, 1);
    k_convgrid<1, true, true, 2><<<dim3(LEN1 / 128, HID / 64, BATCH), 256>>>(
        bufB, erw2, erb2, bufA, bufA, HID, HID, LEN1, 1);

    k_makeC<<<1, 256>>>(erw1 + (size_t)HID * HID * 3, HID, HID * 3, 2);
    k_convgrid<3, true, false, 3><<<dim3(LEN1 / 128, HID / 64, BATCH), 256>>>(
        bufA, erw1 + (size_t)HID * HID * 3, erb1 + HID, nullptr, bufB,
        HID, HID, LEN1, 2);

    k_makeC<<<1, 256>>>(erw2 + (size_t)HID * HID, HID, HID * 1, 3);
    k_convgrid<1, true, true, 4><<<dim3(LEN1 / 128, HID / 64, BATCH), 256>>>(
        bufB, erw2 + (size_t)HID * HID, erb2 + HID, bufA, bufA,
        HID, HID, LEN1, 3);

    k_makeC<<<1, 256>>>(efw, LAT, HID * 3, 4);
    k_convgrid<3, false, false, -1><<<dim3(LEN1 / 128, LAT / 64, BATCH), 256>>>(
        bufA, efw, efb, nullptr, resid, LAT, HID, LEN1, 4);

    // ---------------- residual VQ ----------------
    for (int q = 0; q < NQ; q++) {
        k_vq<<<VQBLOCKS, 256, vq_smem>>>(cbs + (size_t)q * NEMB * LAT,
                                         resid, zq, counts, bsums);
        k_perp<<<1, 512>>>(bsums, counts, scal);
    }

    // ---------------- decoder (tensor-core bf16-split res convs) --------
    k_dect<<<dim3(LEN2 / 128, HID / 64, BATCH), 256>>>(zq, dtw, dtb, bufA);
    for (int i = 0; i < 2; i++) {
        k_convTC<3, true, false><<<dim3(LEN2 / 128, HID / 64, BATCH), 256>>>(
            bufA, drw1 + (size_t)i * HID * HID * 3, drb1 + i * HID, nullptr, bufB,
            HID, HID, LEN2);
        k_convTC<1, true, true><<<dim3(LEN2 / 128, HID / 64, BATCH), 256>>>(
            bufB, drw2 + (size_t)i * HID * HID, drb2 + i * HID, bufA, bufA,
            HID, HID, LEN2);
    }
    k_decfinal<<<dim3(LEN2 / 256, BATCH), 256>>>(bufA, dfw, dfb, dvec);

    // ---------------- output projection + scalars ----------------
    k_outproj<<<NITEMS / 64, 256>>>(dvec, opw, opb, out);
    k_final<<<1, 1>>>(scal, out, out_size);
}

// round 16
// speedup vs baseline: 1.0473x; 1.0212x over previous
#include <cuda_runtime.h>
#include <math.h>

#define BATCH   128
#define NITEMS  8192
#define HID     256
#define LAT     64
#define LEN1    4096
#define LEN2    8192
#define NEMB    512
#define NQ      4
#define MROWS   524288
#define VQBLOCKS 2048

// ---------------- scratch ----------------
__device__ float g_bufA[268435456];
__device__ float g_bufB[268435456];
__device__ float g_res [33554432];
__device__ float g_zq  [33554432];
__device__ float g_dvec[BATCH * NITEMS];
__device__ float g_counts[NEMB];
__device__ float g_scal[2];
__device__ float g_bsums[VQBLOCKS];
__device__ unsigned int g_xmax[8];
__device__ float g_Cval[8][256];

// grid-accumulator MAC (R11/R13 proven): 4 ops/MAC, exact error capture.
#define GMAC(A, E, W, X) do {                                     \
    float _t2 = __fmaf_rn((W), (X), (A));                         \
    float _d  = __fsub_rn(_t2, (A));                              \
    float _e  = __fmaf_rn((W), (X), -_d);                         \
    (E) = __fadd_rn((E), _e);                                     \
    (A) = _t2;                                                    \
} while (0)

__global__ void k_makeC(const float* __restrict__ wt, int CO, int CIK, int slot)
{
    int co = threadIdx.x;
    if (co >= CO) return;
    float l1 = 0.f;
    const float* w = wt + (size_t)co * CIK;
    for (int i = 0; i < CIK; i++) l1 += fabsf(w[i]);
    float xm = __uint_as_float(g_xmax[slot]);
    float B = l1 * xm;
    float C = 1.0f;
    if (B > 0.f) C = ldexpf(1.0f, ilogbf(B) + 3);
    g_Cval[slot][co] = C;
}

__device__ __forceinline__ void blockmax_commit(float m, int slot)
{
    for (int off = 16; off > 0; off >>= 1)
        m = fmaxf(m, __shfl_xor_sync(0xffffffffu, m, off));
    if ((threadIdx.x & 31) == 0)
        atomicMax(&g_xmax[slot], __float_as_uint(m));
}

// =================================================================
// encoder conv1 (fp64-exact, tiny) + fused output max (slot 0)
// =================================================================
__global__ void __launch_bounds__(128) k_enc_conv1(
    const int* __restrict__ uid, const float* __restrict__ mat,
    const float* __restrict__ w, const float* __restrict__ bias,
    float* __restrict__ out)
{
    __shared__ float s_in[258];
    __shared__ float s_w[HID * 4];
    const int b  = blockIdx.y;
    const int l0 = blockIdx.x * 128;
    const int tx = threadIdx.x;
    const float* row = mat + (size_t)uid[b] * NITEMS;
    for (int i = tx; i < 258; i += 128) {
        int g = 2 * l0 - 1 + i;
        s_in[i] = (g >= 0 && g < NITEMS) ? row[g] : 0.f;
    }
    for (int i = tx; i < HID * 4; i += 128) s_w[i] = w[i];
    __syncthreads();
    const double x0 = s_in[2 * tx + 0], x1 = s_in[2 * tx + 1];
    const double x2 = s_in[2 * tx + 2], x3 = s_in[2 * tx + 3];
    const int l = l0 + tx;
    float m = 0.f;
    for (int co = 0; co < HID; co++) {
        double a = 0.0;
        a = fma((double)s_w[co * 4 + 0], x0, a);
        a = fma((double)s_w[co * 4 + 1], x1, a);
        a = fma((double)s_w[co * 4 + 2], x2, a);
        a = fma((double)s_w[co * 4 + 3], x3, a);
        float v = fmaxf(__fadd_rn((float)a, bias[co]), 0.f);
        m = fmaxf(m, v);
        out[((size_t)b * HID + co) * LEN1 + l] = v;
    }
    blockmax_commit(m, 0);
}

// =================================================================
// encoder conv1d, grid-accumulator exact (R13: 64co x 128l, CIC=16)
// =================================================================
template <int K, bool RELU, bool ADDRES, int OUTSLOT>
__global__ void __launch_bounds__(256) k_convgrid(
    const float* __restrict__ in, const float* __restrict__ wt,
    const float* __restrict__ bias, const float* __restrict__ res,
    float* __restrict__ out, int CO, int CI, int L, int slot)
{
    constexpr int PAD = (K - 1) / 2;
    constexpr int LT = 128, COT = 64, CIC = 16;
    constexpr int LW = LT + 2 * PAD;
    __shared__ float s_in[CIC][LW];
    __shared__ float s_w[CIC][K][COT];

    const int b   = blockIdx.z;
    const int co0 = blockIdx.y * COT;
    const int l0  = blockIdx.x * LT;
    const int tid = threadIdx.x;
    const int lq = tid & 15, cq = tid >> 4;
    const int ls = lq * 8, cs = cq * 4;

    float Cc[4];
#pragma unroll
    for (int i = 0; i < 4; i++) Cc[i] = g_Cval[slot][co0 + cs + i];

    float A[4][8], E[4][8];
#pragma unroll
    for (int i = 0; i < 4; i++)
#pragma unroll
        for (int j = 0; j < 8; j++) { A[i][j] = Cc[i]; E[i][j] = 0.f; }

    for (int ci0 = 0; ci0 < CI; ci0 += CIC) {
        for (int idx = tid; idx < CIC * LW; idx += 256) {
            int ci = idx / LW, x = idx % LW;
            int l = l0 - PAD + x;
            float v = 0.f;
            if (l >= 0 && l < L) v = in[((size_t)b * CI + ci0 + ci) * L + l];
            s_in[ci][x] = v;
        }
        for (int idx = tid; idx < CIC * K * COT; idx += 256) {
            int co = idx % COT;
            int k  = (idx / COT) % K;
            int ci = idx / (COT * K);
            s_w[ci][k][co] = wt[((size_t)(co0 + co) * CI + ci0 + ci) * K + k];
        }
        __syncthreads();
#pragma unroll 2
        for (int ci = 0; ci < CIC; ci++) {
            float x[8 + K - 1];
#pragma unroll
            for (int t = 0; t < 8 + K - 1; t++) x[t] = s_in[ci][ls + t];
#pragma unroll
            for (int k = 0; k < K; k++) {
                float4 w4 = *reinterpret_cast<const float4*>(&s_w[ci][k][cs]);
                float wv[4] = {w4.x, w4.y, w4.z, w4.w};
#pragma unroll
                for (int i = 0; i < 4; i++)
#pragma unroll
                    for (int j = 0; j < 8; j++)
                        GMAC(A[i][j], E[i][j], wv[i], x[j + k]);
            }
        }
        __syncthreads();
    }
    float m = 0.f;
#pragma unroll
    for (int i = 0; i < 4; i++) {
        const int co = co0 + cs + i;
        const float bv = bias[co];
        const size_t o = ((size_t)b * CO + co) * L + l0 + ls;
        float v[8];
#pragma unroll
        for (int j = 0; j < 8; j++) {
            float hi = __fsub_rn(A[i][j], Cc[i]);
            v[j] = __fadd_rn(__fadd_rn(hi, E[i][j]), bv);
        }
        if (ADDRES) {
            float4 r0 = *reinterpret_cast<const float4*>(&res[o]);
            float4 r1 = *reinterpret_cast<const float4*>(&res[o + 4]);
            v[0] = __fadd_rn(v[0], r0.x); v[1] = __fadd_rn(v[1], r0.y);
            v[2] = __fadd_rn(v[2], r0.z); v[3] = __fadd_rn(v[3], r0.w);
            v[4] = __fadd_rn(v[4], r1.x); v[5] = __fadd_rn(v[5], r1.y);
            v[6] = __fadd_rn(v[6], r1.z); v[7] = __fadd_rn(v[7], r1.w);
        }
        if (RELU) {
#pragma unroll
            for (int j = 0; j < 8; j++) v[j] = fmaxf(v[j], 0.f);
        }
        if (OUTSLOT >= 0) {
#pragma unroll
            for (int j = 0; j < 8; j++) m = fmaxf(m, v[j]);
        }
        float4 o0 = {v[0], v[1], v[2], v[3]};
        float4 o1 = {v[4], v[5], v[6], v[7]};
        *reinterpret_cast<float4*>(&out[o])     = o0;
        *reinterpret_cast<float4*>(&out[o + 4]) = o1;
    }
    if (OUTSLOT >= 0) blockmax_commit(m, OUTSLOT);
}

// =================================================================
// decoder K=3 conv via Winograd F(4,3): 6 MACs per 4 outputs per ci
// Tile 64co x 128l (32 tiles of 4), 256 thr, thread: 4co x 2 tiles
// =================================================================
__global__ void __launch_bounds__(256) k_convwino(
    const float* __restrict__ in, const float* __restrict__ wt,
    const float* __restrict__ bias, float* __restrict__ out,
    int CO, int CI, int L)
{
    constexpr int LT = 128, COT = 64, CIC = 16;
    constexpr int LW = 132;                 // 130 valid + pad
    __shared__ float s_in[CIC][LW];
    __shared__ float s_U[CIC][6][COT];      // G*w
    __shared__ float s_V[CIC][6][32];       // B^T*d per 4-out tile

    const int b   = blockIdx.z;
    const int co0 = blockIdx.y * COT;
    const int l0  = blockIdx.x * LT;
    const int tid = threadIdx.x;
    const int lq = tid & 15, cq = tid >> 4;
    const int ls = lq * 8, cs = cq * 4;
    const int t0 = lq * 2;                  // first of this thread's 2 tiles

    float M[4][2][6];
#pragma unroll
    for (int i = 0; i < 4; i++)
#pragma unroll
        for (int tt = 0; tt < 2; tt++)
#pragma unroll
            for (int k = 0; k < 6; k++) M[i][tt][k] = 0.f;

    for (int ci0 = 0; ci0 < CI; ci0 += CIC) {
        // load input slab (pad=1): s_in[ci][x] = in[l0-1+x]
        for (int idx = tid; idx < CIC * 130; idx += 256) {
            int ci = idx / 130, x = idx % 130;
            int l = l0 - 1 + x;
            float v = 0.f;
            if (l >= 0 && l < L) v = in[((size_t)b * CI + ci0 + ci) * L + l];
            s_in[ci][x] = v;
        }
        // weight transform U = G w  (16ci*64co entries, 4 per thread)
        for (int idx = tid; idx < CIC * COT; idx += 256) {
            int ci = idx >> 6, co = idx & 63;
            const float* wp = wt + ((size_t)(co0 + co) * CI + ci0 + ci) * 3;
            float w0 = wp[0], w1 = wp[1], w2 = wp[2];
            float s  = w0 + w2;
            float a  = w0 * (1.f / 24.f) + w2 * (1.f / 6.f);
            float bq = w1 * (1.f / 12.f);
            s_U[ci][0][co] = 0.25f * w0;
            s_U[ci][1][co] = (-s - w1) * (1.f / 6.f);
            s_U[ci][2][co] = (-s + w1) * (1.f / 6.f);
            s_U[ci][3][co] = a + bq;
            s_U[ci][4][co] = a - bq;
            s_U[ci][5][co] = w2;
        }
        __syncthreads();
        // input transform V = B^T d  (16ci*32tiles, 2 per thread)
        for (int idx = tid; idx < CIC * 32; idx += 256) {
            int ci = idx >> 5, t = idx & 31;
            const float* d = &s_in[ci][4 * t];
            float d0 = d[0], d1 = d[1], d2 = d[2];
            float d3 = d[3], d4 = d[4], d5 = d[5];
            float s1 = d1 + d2, s2 = d3 + d4;
            float q1 = d1 - d2, q2 = d4 - d3;
            float r1 = d3 - d1, r2 = d4 - d2;
            s_V[ci][0][t] = fmaf(4.f, d0, fmaf(-5.f, d2, d4));
            s_V[ci][1][t] = fmaf(-4.f, s1, s2);
            s_V[ci][2][t] = fmaf(4.f, q1, q2);
            s_V[ci][3][t] = fmaf(2.f, r1, r2);
            s_V[ci][4][t] = fmaf(-2.f, r1, r2);
            s_V[ci][5][t] = fmaf(4.f, d1, fmaf(-5.f, d3, d5));
        }
        __syncthreads();
        // elementwise accumulate in transform domain
#pragma unroll 2
        for (int ci = 0; ci < CIC; ci++) {
#pragma unroll
            for (int k = 0; k < 6; k++) {
                float2 v2 = *reinterpret_cast<const float2*>(&s_V[ci][k][t0]);
                float4 u4 = *reinterpret_cast<const float4*>(&s_U[ci][k][cs]);
                float uu[4] = {u4.x, u4.y, u4.z, u4.w};
#pragma unroll
                for (int i = 0; i < 4; i++) {
                    M[i][0][k] = fmaf(uu[i], v2.x, M[i][0][k]);
                    M[i][1][k] = fmaf(uu[i], v2.y, M[i][1][k]);
                }
            }
        }
        __syncthreads();
    }

    // output transform + bias + relu + store
#pragma unroll
    for (int i = 0; i < 4; i++) {
        const int co = co0 + cs + i;
        const float bv = bias[co];
        const size_t o = ((size_t)b * CO + co) * L + l0 + ls;
        float v[8];
#pragma unroll
        for (int tt = 0; tt < 2; tt++) {
            float m0 = M[i][tt][0], m1 = M[i][tt][1], m2 = M[i][tt][2];
            float m3 = M[i][tt][3], m4 = M[i][tt][4], m5 = M[i][tt][5];
            float p = m1 + m2, q2 = m1 - m2;
            float r = m3 + m4, s2 = m3 - m4;
            v[tt * 4 + 0] = (m0 + p) + r;
            v[tt * 4 + 1] = fmaf(2.f, s2, q2);
            v[tt * 4 + 2] = fmaf(4.f, r, p);
            v[tt * 4 + 3] = fmaf(8.f, s2, q2) + m5;
        }
#pragma unroll
        for (int j = 0; j < 8; j++) v[j] = fmaxf(v[j] + bv, 0.f);
        float4 o0 = {v[0], v[1], v[2], v[3]};
        float4 o1 = {v[4], v[5], v[6], v[7]};
        *reinterpret_cast<float4*>(&out[o])     = o0;
        *reinterpret_cast<float4*>(&out[o + 4]) = o1;
    }
}

// =================================================================
// decoder conv1d (fp32 scalar, R13), K=1 path (relu + residual)
// =================================================================
template <int K, bool RELU, bool ADDRES>
__global__ void __launch_bounds__(256) k_conv(
    const float* __restrict__ in, const float* __restrict__ wt,
    const float* __restrict__ bias, const float* __restrict__ res,
    float* __restrict__ out, int CO, int CI, int L)
{
    constexpr int PAD = (K - 1) / 2;
    constexpr int LT = 128, COT = 64, CIC = 16;
    constexpr int LW = LT + 2 * PAD;
    __shared__ float s_in[CIC][LW];
    __shared__ float s_w[CIC][K][COT];

    const int b   = blockIdx.z;
    const int co0 = blockIdx.y * COT;
    const int l0  = blockIdx.x * LT;
    const int tid = threadIdx.x;
    const int lq = tid & 15, cq = tid >> 4;
    const int ls = lq * 8, cs = cq * 4;

    float acc[4][8];
#pragma unroll
    for (int i = 0; i < 4; i++)
#pragma unroll
        for (int j = 0; j < 8; j++) acc[i][j] = 0.f;

    for (int ci0 = 0; ci0 < CI; ci0 += CIC) {
        for (int idx = tid; idx < CIC * LW; idx += 256) {
            int ci = idx / LW, x = idx % LW;
            int l = l0 - PAD + x;
            float v = 0.f;
            if (l >= 0 && l < L) v = in[((size_t)b * CI + ci0 + ci) * L + l];
            s_in[ci][x] = v;
        }
        for (int idx = tid; idx < CIC * K * COT; idx += 256) {
            int co = idx % COT;
            int k  = (idx / COT) % K;
            int ci = idx / (COT * K);
            s_w[ci][k][co] = wt[((size_t)(co0 + co) * CI + ci0 + ci) * K + k];
        }
        __syncthreads();
#pragma unroll 4
        for (int ci = 0; ci < CIC; ci++) {
            float x[8 + K - 1];
#pragma unroll
            for (int t = 0; t < 8 + K - 1; t++) x[t] = s_in[ci][ls + t];
#pragma unroll
            for (int k = 0; k < K; k++) {
                float4 w4 = *reinterpret_cast<const float4*>(&s_w[ci][k][cs]);
                float wv[4] = {w4.x, w4.y, w4.z, w4.w};
#pragma unroll
                for (int i = 0; i < 4; i++)
#pragma unroll
                    for (int j = 0; j < 8; j++)
                        acc[i][j] = fmaf(wv[i], x[j + k], acc[i][j]);
            }
        }
        __syncthreads();
    }
#pragma unroll
    for (int i = 0; i < 4; i++) {
        const int co = co0 + cs + i;
        const float bv = bias[co];
        const size_t o = ((size_t)b * CO + co) * L + l0 + ls;
        float v[8];
#pragma unroll
        for (int j = 0; j < 8; j++) v[j] = __fadd_rn(acc[i][j], bv);
        if (ADDRES) {
            float4 r0 = *reinterpret_cast<const float4*>(&res[o]);
            float4 r1 = *reinterpret_cast<const float4*>(&res[o + 4]);
            v[0] = __fadd_rn(v[0], r0.x); v[1] = __fadd_rn(v[1], r0.y);
            v[2] = __fadd_rn(v[2], r0.z); v[3] = __fadd_rn(v[3], r0.w);
            v[4] = __fadd_rn(v[4], r1.x); v[5] = __fadd_rn(v[5], r1.y);
            v[6] = __fadd_rn(v[6], r1.z); v[7] = __fadd_rn(v[7], r1.w);
        }
        if (RELU) {
#pragma unroll
            for (int j = 0; j < 8; j++) v[j] = fmaxf(v[j], 0.f);
        }
        float4 o0 = {v[0], v[1], v[2], v[3]};
        float4 o1 = {v[4], v[5], v[6], v[7]};
        *reinterpret_cast<float4*>(&out[o])     = o0;
        *reinterpret_cast<float4*>(&out[o + 4]) = o1;
    }
}

// =================================================================
// VQ: single-pass fp32 screen + exact fp64 refine
// =================================================================
__global__ void __launch_bounds__(256) k_vq(
    const float* __restrict__ cb, float* __restrict__ resid,
    float* __restrict__ zq, float* __restrict__ counts,
    float* __restrict__ bsums)
{
    extern __shared__ float sm[];
    float* s_code = sm;
    float* s_cn   = sm + NEMB * LAT;
    const int tid = threadIdx.x;

    for (int idx = tid; idx < NEMB * LAT / 4; idx += 256)
        reinterpret_cast<float4*>(s_code)[idx] =
            reinterpret_cast<const float4*>(cb)[idx];
    __syncthreads();
    for (int e = tid; e < NEMB; e += 256) {
        const float* c = s_code + e * LAT;
        double s = 0.0;
#pragma unroll
        for (int j = 0; j < 64; j++) s = fma((double)c[j], (double)c[j], s);
        s_cn[e] = (float)s;
    }
    __syncthreads();

    const size_t m = (size_t)blockIdx.x * 256 + tid;
    float r[64];
    {
        const float4* g = reinterpret_cast<const float4*>(resid + m * 64);
        float4* rr = reinterpret_cast<float4*>(r);
#pragma unroll
        for (int t = 0; t < 16; t++) rr[t] = g[t];
    }
    double rn64 = 0.0;
#pragma unroll
    for (int j = 0; j < 64; j++) rn64 = fma((double)r[j], (double)r[j], rn64);
    const float rn = (float)rn64;

    float sabs = 0.f;
#pragma unroll
    for (int j = 0; j < 64; j++) sabs = __fadd_rn(sabs, fabsf(r[j]));

    const float margin = 4.8e-7f * rn + 6.4e-8f * sabs + 1e-8f;

    float best_ka = 3.4e38f;
    int   cand[16];
    int   nc = 0;
    bool  overflow = false;
    for (int e = 0; e < NEMB; e += 4) {
        const float4* c0 = reinterpret_cast<const float4*>(s_code + (e + 0) * LAT);
        const float4* c1 = reinterpret_cast<const float4*>(s_code + (e + 1) * LAT);
        const float4* c2 = reinterpret_cast<const float4*>(s_code + (e + 2) * LAT);
        const float4* c3 = reinterpret_cast<const float4*>(s_code + (e + 3) * LAT);
        float d0 = 0.f, d1 = 0.f, d2 = 0.f, d3 = 0.f;
#pragma unroll
        for (int t = 0; t < 16; t++) {
            float4 a0 = c0[t], a1 = c1[t], a2 = c2[t], a3 = c3[t];
            float x0 = r[t*4+0], x1 = r[t*4+1], x2 = r[t*4+2], x3 = r[t*4+3];
            d0 = fmaf(a0.x, x0, d0); d0 = fmaf(a0.y, x1, d0);
            d0 = fmaf(a0.z, x2, d0); d0 = fmaf(a0.w, x3, d0);
            d1 = fmaf(a1.x, x0, d1); d1 = fmaf(a1.y, x1, d1);
            d1 = fmaf(a1.z, x2, d1); d1 = fmaf(a1.w, x3, d1);
            d2 = fmaf(a2.x, x0, d2); d2 = fmaf(a2.y, x1, d2);
            d2 = fmaf(a2.z, x2, d2); d2 = fmaf(a2.w, x3, d2);
            d3 = fmaf(a3.x, x0, d3); d3 = fmaf(a3.y, x1, d3);
            d3 = fmaf(a3.z, x2, d3); d3 = fmaf(a3.w, x3, d3);
        }
        float ka[4];
        ka[0] = __fsub_rn(__fadd_rn(rn, s_cn[e + 0]), __fmul_rn(2.f, d0));
        ka[1] = __fsub_rn(__fadd_rn(rn, s_cn[e + 1]), __fmul_rn(2.f, d1));
        ka[2] = __fsub_rn(__fadd_rn(rn, s_cn[e + 2]), __fmul_rn(2.f, d2));
        ka[3] = __fsub_rn(__fadd_rn(rn, s_cn[e + 3]), __fmul_rn(2.f, d3));
#pragma unroll
        for (int i = 0; i < 4; i++) {
            if (ka[i] < best_ka) best_ka = ka[i];
            if (ka[i] <= best_ka + margin) {
                if (nc < 16) cand[nc++] = e + i;
                else overflow = true;
            }
        }
    }

    float best = 3.4e38f;
    int bi = 0;
    if (!overflow) {
        for (int ci = 0; ci < nc; ci++) {
            int e = cand[ci];
            const float* c = s_code + (size_t)e * LAT;
            double dd = 0.0;
#pragma unroll
            for (int j = 0; j < 64; j++)
                dd = fma((double)c[j], (double)r[j], dd);
            float dot = (float)dd;
            float dist = __fsub_rn(__fadd_rn(rn, s_cn[e]),
                                   __fmul_rn(2.f, dot));
            if (dist < best) { best = dist; bi = e; }
        }
    } else {
        for (int e = 0; e < NEMB; e++) {
            const float* c = s_code + (size_t)e * LAT;
            double dd = 0.0;
#pragma unroll
            for (int j = 0; j < 64; j++)
                dd = fma((double)c[j], (double)r[j], dd);
            float dot = (float)dd;
            float dist = __fsub_rn(__fadd_rn(rn, s_cn[e]),
                                   __fmul_rn(2.f, dot));
            if (dist < best) { best = dist; bi = e; }
        }
    }

    float sq = 0.f;
    {
        const float* c = s_code + bi * LAT;
        float4* rg = reinterpret_cast<float4*>(resid + m * 64);
        float4* zg = reinterpret_cast<float4*>(zq + m * 64);
#pragma unroll
        for (int t = 0; t < 16; t++) {
            float4 zv = zg[t];
            float q[4] = {c[t*4+0], c[t*4+1], c[t*4+2], c[t*4+3]};
            float rv[4] = {r[t*4+0], r[t*4+1], r[t*4+2], r[t*4+3]};
            float4 nr, nz;
            float o_r[4], o_z[4];
#pragma unroll
            for (int u = 0; u < 4; u++) {
                float d  = __fsub_rn(q[u], rv[u]);
                sq = __fadd_rn(sq, __fmul_rn(d, d));
                float qs = __fadd_rn(rv[u], d);
                o_r[u] = __fsub_rn(rv[u], qs);
                o_z[u] = __fadd_rn((&zv.x)[u], qs);
            }
            nr.x = o_r[0]; nr.y = o_r[1]; nr.z = o_r[2]; nr.w = o_r[3];
            nz.x = o_z[0]; nz.y = o_z[1]; nz.z = o_z[2]; nz.w = o_z[3];
            rg[t] = nr; zg[t] = nz;
        }
    }
    atomicAdd(&counts[bi], 1.f);

    __shared__ float red[256];
    red[tid] = sq;
    __syncthreads();
    for (int s = 128; s > 0; s >>= 1) {
        if (tid < s) red[tid] += red[tid + s];
        __syncthreads();
    }
    if (tid == 0) bsums[blockIdx.x] = red[0];
}

__global__ void k_perp(const float* __restrict__ bsums, float* __restrict__ counts,
                       float* __restrict__ scal)
{
    __shared__ float red[512];
    __shared__ float red2[512];
    const int t = threadIdx.x;
    float c = counts[t];
    float avg = c * (1.0f / (float)MROWS);
    red[t] = avg * logf(avg + 1e-10f);
    float s2 = 0.f;
    for (int i = t; i < VQBLOCKS; i += 512) s2 += bsums[i];
    red2[t] = s2;
    __syncthreads();
    for (int s = 256; s > 0; s >>= 1) {
        if (t < s) { red[t] += red[t + s]; red2[t] += red2[t + s]; }
        __syncthreads();
    }
    if (t == 0) {
        scal[1] += expf(-red[0]);
        scal[0] += red2[0];
    }
    counts[t] = 0.f;
}

// =================================================================
// decoder ConvTranspose1d(64->256, K=4, s2, p1) + relu (fp32 scalar)
// =================================================================
__global__ void __launch_bounds__(256) k_dect(
    const float* __restrict__ in, const float* __restrict__ wt,
    const float* __restrict__ bias, float* __restrict__ out)
{
    constexpr int OT = 128, COT = 64, CIC = 32;
    __shared__ float s_in[CIC][66];
    __shared__ float s_w[CIC][4][COT];
    const int b   = blockIdx.z;
    const int co0 = blockIdx.y * COT;
    const int o0  = blockIdx.x * OT;
    const int tid = threadIdx.x;
    const int lq = tid & 15, cq = tid >> 4;
    const int os = lq * 8, cs = cq * 4;
    const int lbase = o0 / 2 - 1;

    float acc[4][8];
#pragma unroll
    for (int i = 0; i < 4; i++)
#pragma unroll
        for (int j = 0; j < 8; j++) acc[i][j] = 0.f;

    for (int ci0 = 0; ci0 < LAT; ci0 += CIC) {
        for (int idx = tid; idx < CIC * 66; idx += 256) {
            int ci = idx / 66, x = idx % 66;
            int l = lbase + x;
            float v = 0.f;
            if (l >= 0 && l < LEN1) v = in[((size_t)b * LAT + ci0 + ci) * LEN1 + l];
            s_in[ci][x] = v;
        }
        for (int idx = tid; idx < CIC * 4 * COT; idx += 256) {
            int co = idx & 63;
            int k  = (idx >> 6) & 3;
            int ci = idx >> 8;
            s_w[ci][k][co] = wt[((size_t)(ci0 + ci) * HID + co0 + co) * 4 + k];
        }
        __syncthreads();
#pragma unroll 4
        for (int ci = 0; ci < CIC; ci++) {
            float x[6];
#pragma unroll
            for (int t = 0; t < 6; t++) x[t] = s_in[ci][(os >> 1) + t];
            float4 W0 = *reinterpret_cast<const float4*>(&s_w[ci][0][cs]);
            float4 W1 = *reinterpret_cast<const float4*>(&s_w[ci][1][cs]);
            float4 W2 = *reinterpret_cast<const float4*>(&s_w[ci][2][cs]);
            float4 W3 = *reinterpret_cast<const float4*>(&s_w[ci][3][cs]);
            float wa[4][4] = {{W0.x, W0.y, W0.z, W0.w},
                              {W1.x, W1.y, W1.z, W1.w},
                              {W2.x, W2.y, W2.z, W2.w},
                              {W3.x, W3.y, W3.z, W3.w}};
#pragma unroll
            for (int jj = 0; jj < 4; jj++) {
                float xe0 = x[jj], xe1 = x[jj + 1], xo2 = x[jj + 2];
#pragma unroll
                for (int i = 0; i < 4; i++) {
                    acc[i][2 * jj]     = fmaf(wa[1][i], xe1, fmaf(wa[3][i], xe0, acc[i][2 * jj]));
                    acc[i][2 * jj + 1] = fmaf(wa[0][i], xo2, fmaf(wa[2][i], xe1, acc[i][2 * jj + 1]));
                }
            }
        }
        __syncthreads();
    }
#pragma unroll
    for (int i = 0; i < 4; i++) {
        const int co = co0 + cs + i;
        const float bv = bias[co];
        const size_t o = ((size_t)b * HID + co) * LEN2 + o0 + os;
        float v[8];
#pragma unroll
        for (int j = 0; j < 8; j++) v[j] = fmaxf(__fadd_rn(acc[i][j], bv), 0.f);
        float4 q0 = {v[0], v[1], v[2], v[3]};
        float4 q1 = {v[4], v[5], v[6], v[7]};
        *reinterpret_cast<float4*>(&out[o])     = q0;
        *reinterpret_cast<float4*>(&out[o + 4]) = q1;
    }
}

// =================================================================
// decoder ConvTranspose1d(256->1, K=3, s1, p1) (fp32)
// =================================================================
__global__ void __launch_bounds__(256) k_decfinal(
    const float* __restrict__ in, const float* __restrict__ wt,
    const float* __restrict__ bias, float* __restrict__ out)
{
    __shared__ float s_w[HID * 3];
    __shared__ float s_in[32][258];
    const int b  = blockIdx.y;
    const int o0 = blockIdx.x * 256;
    const int tx = threadIdx.x;
    for (int i = tx; i < HID * 3; i += 256) s_w[i] = wt[i];
    float acc = 0.f;
    for (int cc = 0; cc < HID; cc += 32) {
        __syncthreads();
        for (int idx = tx; idx < 32 * 258; idx += 256) {
            int ci = idx / 258, x = idx % 258;
            int l = o0 - 1 + x;
            s_in[ci][x] = (l >= 0 && l < LEN2)
                        ? in[((size_t)b * HID + cc + ci) * LEN2 + l] : 0.f;
        }
        __syncthreads();
#pragma unroll 8
        for (int ci = 0; ci < 32; ci++) {
            acc = fmaf(s_w[(cc + ci) * 3 + 0], s_in[ci][tx + 2], acc);
            acc = fmaf(s_w[(cc + ci) * 3 + 1], s_in[ci][tx + 1], acc);
            acc = fmaf(s_w[(cc + ci) * 3 + 2], s_in[ci][tx + 0], acc);
        }
    }
    out[(size_t)b * LEN2 + o0 + tx] = __fadd_rn(acc, bias[0]);
}

// =================================================================
// out projection (fp32 scalar)
// =================================================================
__global__ void __launch_bounds__(256) k_outproj(
    const float* __restrict__ dv, const float* __restrict__ W,
    const float* __restrict__ bias, float* __restrict__ out)
{
    constexpr int KC = 32;
    __shared__ float s_d[KC][136];
    __shared__ float s_w[KC][68];
    const int j0  = blockIdx.x * 64;
    const int tid = threadIdx.x;
    const int bq = tid & 15, jq = tid >> 4;
    const int bs = bq * 8, js = jq * 4;
    float acc[8][4];
#pragma unroll
    for (int i = 0; i < 8; i++)
#pragma unroll
        for (int j = 0; j < 4; j++) acc[i][j] = 0.f;

    for (int k0 = 0; k0 < NITEMS; k0 += KC) {
        for (int idx = tid; idx < KC * 128; idx += 256) {
            int bb = idx >> 5, k = idx & 31;
            s_d[k][bb] = dv[(size_t)bb * NITEMS + k0 + k];
        }
        for (int idx = tid; idx < KC * 64; idx += 256) {
            int j = idx >> 5, k = idx & 31;
            s_w[k][j] = W[(size_t)(j0 + j) * NITEMS + k0 + k];
        }
        __syncthreads();
#pragma unroll
        for (int k = 0; k < KC; k++) {
            float4 w4 = *reinterpret_cast<const float4*>(&s_w[k][js]);
            float xb[8];
            *reinterpret_cast<float4*>(&xb[0]) = *reinterpret_cast<const float4*>(&s_d[k][bs]);
            *reinterpret_cast<float4*>(&xb[4]) = *reinterpret_cast<const float4*>(&s_d[k][bs + 4]);
            float wv[4] = {w4.x, w4.y, w4.z, w4.w};
#pragma unroll
            for (int i = 0; i < 8; i++)
#pragma unroll
                for (int j = 0; j < 4; j++)
                    acc[i][j] = fmaf(xb[i], wv[j], acc[i][j]);
        }
        __syncthreads();
    }
#pragma unroll
    for (int i = 0; i < 8; i++) {
#pragma unroll
        for (int j = 0; j < 4; j++)
            out[(size_t)(bs + i) * NITEMS + j0 + js + j] =
                __fadd_rn(acc[i][j], bias[j0 + js + j]);
    }
}

__global__ void k_final(const float* __restrict__ scal, float* __restrict__ out, int out_size)
{
    if (out_size >= BATCH * NITEMS + 2) {
        out[BATCH * NITEMS + 0] = 1.25f * scal[0] * (1.0f / 33554432.0f);
        out[BATCH * NITEMS + 1] = scal[1] * 0.25f;
    }
}

// =================================================================
extern "C" void kernel_launch(void* const* d_in, const int* in_sizes, int n_in,
                              void* d_out, int out_size)
{
    const int*   uid  = (const int*)  d_in[0];
    const float* mat  = (const float*)d_in[1];
    const float* ecw  = (const float*)d_in[2];
    const float* ecb  = (const float*)d_in[3];
    const float* erw1 = (const float*)d_in[4];
    const float* erb1 = (const float*)d_in[5];
    const float* erw2 = (const float*)d_in[6];
    const float* erb2 = (const float*)d_in[7];
    const float* efw  = (const float*)d_in[8];
    const float* efb  = (const float*)d_in[9];
    const float* cbs  = (const float*)d_in[10];
    const float* dtw  = (const float*)d_in[11];
    const float* dtb  = (const float*)d_in[12];
    const float* drw1 = (const float*)d_in[13];
    const float* drb1 = (const float*)d_in[14];
    const float* drw2 = (const float*)d_in[15];
    const float* drb2 = (const float*)d_in[16];
    const float* dfw  = (const float*)d_in[17];
    const float* dfb  = (const float*)d_in[18];
    const float* opw  = (const float*)d_in[19];
    const float* opb  = (const float*)d_in[20];
    float* out = (float*)d_out;

    float *bufA, *bufB, *resid, *zq, *dvec, *counts, *scal, *bsums;
    unsigned int* xmax;
    cudaGetSymbolAddress((void**)&bufA,   g_bufA);
    cudaGetSymbolAddress((void**)&bufB,   g_bufB);
    cudaGetSymbolAddress((void**)&resid,  g_res);
    cudaGetSymbolAddress((void**)&zq,     g_zq);
    cudaGetSymbolAddress((void**)&dvec,   g_dvec);
    cudaGetSymbolAddress((void**)&counts, g_counts);
    cudaGetSymbolAddress((void**)&scal,   g_scal);
    cudaGetSymbolAddress((void**)&bsums,  g_bsums);
    cudaGetSymbolAddress((void**)&xmax,   g_xmax);

    const int vq_smem = (NEMB * LAT + NEMB) * (int)sizeof(float);
    cudaFuncSetAttribute(k_vq, cudaFuncAttributeMaxDynamicSharedMemorySize, vq_smem);

    cudaMemsetAsync(zq, 0, (size_t)33554432 * sizeof(float), 0);
    cudaMemsetAsync(scal, 0, 2 * sizeof(float), 0);
    cudaMemsetAsync(counts, 0, NEMB * sizeof(float), 0);
    cudaMemsetAsync(xmax, 0, 8 * sizeof(unsigned int), 0);

    // ---------------- encoder (grid-accumulator exact, fused max) -------
    k_enc_conv1<<<dim3(LEN1 / 128, BATCH), 128>>>(uid, mat, ecw, ecb, bufA);

    k_makeC<<<1, 256>>>(erw1, HID, HID * 3, 0);
    k_convgrid<3, true, false, 1><<<dim3(LEN1 / 128, HID / 64, BATCH), 256>>>(
        bufA, erw1, erb1, nullptr, bufB, HID, HID, LEN1, 0);

    k_makeC<<<1, 256>>>(erw2, HID, HID * 1, 1);
    k_convgrid<1, true, true, 2><<<dim3(LEN1 / 128, HID / 64, BATCH), 256>>>(
        bufB, erw2, erb2, bufA, bufA, HID, HID, LEN1, 1);

    k_makeC<<<1, 256>>>(erw1 + (size_t)HID * HID * 3, HID, HID * 3, 2);
    k_convgrid<3, true, false, 3><<<dim3(LEN1 / 128, HID / 64, BATCH), 256>>>(
        bufA, erw1 + (size_t)HID * HID * 3, erb1 + HID, nullptr, bufB,
        HID, HID, LEN1, 2);

    k_makeC<<<1, 256>>>(erw2 + (size_t)HID * HID, HID, HID * 1, 3);
    k_convgrid<1, true, true, 4><<<dim3(LEN1 / 128, HID / 64, BATCH), 256>>>(
        bufB, erw2 + (size_t)HID * HID, erb2 + HID, bufA, bufA,
        HID, HID, LEN1, 3);

    k_makeC<<<1, 256>>>(efw, LAT, HID * 3, 4);
    k_convgrid<3, false, false, -1><<<dim3(LEN1 / 128, LAT / 64, BATCH), 256>>>(
        bufA, efw, efb, nullptr, resid, LAT, HID, LEN1, 4);

    // ---------------- residual VQ ----------------
    for (int q = 0; q < NQ; q++) {
        k_vq<<<VQBLOCKS, 256, vq_smem>>>(cbs + (size_t)q * NEMB * LAT,
                                         resid, zq, counts, bsums);
        k_perp<<<1, 512>>>(bsums, counts, scal);
    }

    // ---------------- decoder (Winograd K=3, scalar K=1) ----------------
    k_dect<<<dim3(LEN2 / 128, HID / 64, BATCH), 256>>>(zq, dtw, dtb, bufA);
    for (int i = 0; i < 2; i++) {
        k_convwino<<<dim3(LEN2 / 128, HID / 64, BATCH), 256>>>(
            bufA, drw1 + (size_t)i * HID * HID * 3, drb1 + i * HID, bufB,
            HID, HID, LEN2);
        k_conv<1, true, true><<<dim3(LEN2 / 128, HID / 64, BATCH), 256>>>(
            bufB, drw2 + (size_t)i * HID * HID, drb2 + i * HID, bufA, bufA,
            HID, HID, LEN2);
    }
    k_decfinal<<<dim3(LEN2 / 256, BATCH), 256>>>(bufA, dfw, dfb, dvec);

    // ---------------- output projection + scalars ----------------
    k_outproj<<<NITEMS / 64, 256>>>(dvec, opw, opb, out);
    k_final<<<1, 1>>>(scal, out, out_size);
}

// round 17
// speedup vs baseline: 1.0896x; 1.0404x over previous
#include <cuda_runtime.h>
#include <math.h>

#define BATCH   128
#define NITEMS  8192
#define HID     256
#define LAT     64
#define LEN1    4096
#define LEN2    8192
#define NEMB    512
#define NQ      4
#define MROWS   524288
#define VQBLOCKS 2048

// ---------------- scratch ----------------
__device__ float g_bufA[268435456];
__device__ float g_bufB[268435456];
__device__ float g_res [33554432];
__device__ float g_zq  [33554432];
__device__ float g_dvec[BATCH * NITEMS];
__device__ float g_counts[NEMB];
__device__ float g_scal[2];
__device__ float g_bsums[VQBLOCKS];
__device__ unsigned int g_xmax[8];
__device__ float g_Cval[8][256];
__device__ float g_Uw[6 * 256 * 256];   // winograd weight transform [ci][k][co]

// grid-accumulator MAC (R11/R13 proven): 4 ops/MAC, exact error capture.
#define GMAC(A, E, W, X) do {                                     \
    float _t2 = __fmaf_rn((W), (X), (A));                         \
    float _d  = __fsub_rn(_t2, (A));                              \
    float _e  = __fmaf_rn((W), (X), -_d);                         \
    (E) = __fadd_rn((E), _e);                                     \
    (A) = _t2;                                                    \
} while (0)

__global__ void k_makeC(const float* __restrict__ wt, int CO, int CIK, int slot)
{
    int co = threadIdx.x;
    if (co >= CO) return;
    float l1 = 0.f;
    const float* w = wt + (size_t)co * CIK;
    for (int i = 0; i < CIK; i++) l1 += fabsf(w[i]);
    float xm = __uint_as_float(g_xmax[slot]);
    float B = l1 * xm;
    float C = 1.0f;
    if (B > 0.f) C = ldexpf(1.0f, ilogbf(B) + 3);
    g_Cval[slot][co] = C;
}

__device__ __forceinline__ void blockmax_commit(float m, int slot)
{
    for (int off = 16; off > 0; off >>= 1)
        m = fmaxf(m, __shfl_xor_sync(0xffffffffu, m, off));
    if ((threadIdx.x & 31) == 0)
        atomicMax(&g_xmax[slot], __float_as_uint(m));
}

// winograd weight transform U = G w (per layer, once; same formulas as in-kernel)
__global__ void k_wtrans(const float* __restrict__ wt, float* __restrict__ Ug, int CI)
{
    int co = threadIdx.x;          // 256
    int ci = blockIdx.x;           // 256
    const float* wp = wt + ((size_t)co * CI + ci) * 3;
    float w0 = wp[0], w1 = wp[1], w2 = wp[2];
    float s  = w0 + w2;
    float a  = w0 * (1.f / 24.f) + w2 * (1.f / 6.f);
    float bq = w1 * (1.f / 12.f);
    float u[6];
    u[0] = 0.25f * w0;
    u[1] = (-s - w1) * (1.f / 6.f);
    u[2] = (-s + w1) * (1.f / 6.f);
    u[3] = a + bq;
    u[4] = a - bq;
    u[5] = w2;
#pragma unroll
    for (int k = 0; k < 6; k++)
        Ug[((size_t)ci * 6 + k) * 256 + co] = u[k];
}

// =================================================================
// encoder conv1 (fp64-exact, tiny) + fused output max (slot 0)
// =================================================================
__global__ void __launch_bounds__(128) k_enc_conv1(
    const int* __restrict__ uid, const float* __restrict__ mat,
    const float* __restrict__ w, const float* __restrict__ bias,
    float* __restrict__ out)
{
    __shared__ float s_in[258];
    __shared__ float s_w[HID * 4];
    const int b  = blockIdx.y;
    const int l0 = blockIdx.x * 128;
    const int tx = threadIdx.x;
    const float* row = mat + (size_t)uid[b] * NITEMS;
    for (int i = tx; i < 258; i += 128) {
        int g = 2 * l0 - 1 + i;
        s_in[i] = (g >= 0 && g < NITEMS) ? row[g] : 0.f;
    }
    for (int i = tx; i < HID * 4; i += 128) s_w[i] = w[i];
    __syncthreads();
    const double x0 = s_in[2 * tx + 0], x1 = s_in[2 * tx + 1];
    const double x2 = s_in[2 * tx + 2], x3 = s_in[2 * tx + 3];
    const int l = l0 + tx;
    float m = 0.f;
    for (int co = 0; co < HID; co++) {
        double a = 0.0;
        a = fma((double)s_w[co * 4 + 0], x0, a);
        a = fma((double)s_w[co * 4 + 1], x1, a);
        a = fma((double)s_w[co * 4 + 2], x2, a);
        a = fma((double)s_w[co * 4 + 3], x3, a);
        float v = fmaxf(__fadd_rn((float)a, bias[co]), 0.f);
        m = fmaxf(m, v);
        out[((size_t)b * HID + co) * LEN1 + l] = v;
    }
    blockmax_commit(m, 0);
}

// =================================================================
// encoder conv1d, grid-accumulator exact (R13: 64co x 128l, CIC=16)
// =================================================================
template <int K, bool RELU, bool ADDRES, int OUTSLOT>
__global__ void __launch_bounds__(256) k_convgrid(
    const float* __restrict__ in, const float* __restrict__ wt,
    const float* __restrict__ bias, const float* __restrict__ res,
    float* __restrict__ out, int CO, int CI, int L, int slot)
{
    constexpr int PAD = (K - 1) / 2;
    constexpr int LT = 128, COT = 64, CIC = 16;
    constexpr int LW = LT + 2 * PAD;
    __shared__ float s_in[CIC][LW];
    __shared__ float s_w[CIC][K][COT];

    const int b   = blockIdx.z;
    const int co0 = blockIdx.y * COT;
    const int l0  = blockIdx.x * LT;
    const int tid = threadIdx.x;
    const int lq = tid & 15, cq = tid >> 4;
    const int ls = lq * 8, cs = cq * 4;

    float Cc[4];
#pragma unroll
    for (int i = 0; i < 4; i++) Cc[i] = g_Cval[slot][co0 + cs + i];

    float A[4][8], E[4][8];
#pragma unroll
    for (int i = 0; i < 4; i++)
#pragma unroll
        for (int j = 0; j < 8; j++) { A[i][j] = Cc[i]; E[i][j] = 0.f; }

    for (int ci0 = 0; ci0 < CI; ci0 += CIC) {
        for (int idx = tid; idx < CIC * LW; idx += 256) {
            int ci = idx / LW, x = idx % LW;
            int l = l0 - PAD + x;
            float v = 0.f;
            if (l >= 0 && l < L) v = in[((size_t)b * CI + ci0 + ci) * L + l];
            s_in[ci][x] = v;
        }
        for (int idx = tid; idx < CIC * K * COT; idx += 256) {
            int co = idx % COT;
            int k  = (idx / COT) % K;
            int ci = idx / (COT * K);
            s_w[ci][k][co] = wt[((size_t)(co0 + co) * CI + ci0 + ci) * K + k];
        }
        __syncthreads();
#pragma unroll 2
        for (int ci = 0; ci < CIC; ci++) {
            float x[8 + K - 1];
#pragma unroll
            for (int t = 0; t < 8 + K - 1; t++) x[t] = s_in[ci][ls + t];
#pragma unroll
            for (int k = 0; k < K; k++) {
                float4 w4 = *reinterpret_cast<const float4*>(&s_w[ci][k][cs]);
                float wv[4] = {w4.x, w4.y, w4.z, w4.w};
#pragma unroll
                for (int i = 0; i < 4; i++)
#pragma unroll
                    for (int j = 0; j < 8; j++)
                        GMAC(A[i][j], E[i][j], wv[i], x[j + k]);
            }
        }
        __syncthreads();
    }
    float m = 0.f;
#pragma unroll
    for (int i = 0; i < 4; i++) {
        const int co = co0 + cs + i;
        const float bv = bias[co];
        const size_t o = ((size_t)b * CO + co) * L + l0 + ls;
        float v[8];
#pragma unroll
        for (int j = 0; j < 8; j++) {
            float hi = __fsub_rn(A[i][j], Cc[i]);
            v[j] = __fadd_rn(__fadd_rn(hi, E[i][j]), bv);
        }
        if (ADDRES) {
            float4 r0 = *reinterpret_cast<const float4*>(&res[o]);
            float4 r1 = *reinterpret_cast<const float4*>(&res[o + 4]);
            v[0] = __fadd_rn(v[0], r0.x); v[1] = __fadd_rn(v[1], r0.y);
            v[2] = __fadd_rn(v[2], r0.z); v[3] = __fadd_rn(v[3], r0.w);
            v[4] = __fadd_rn(v[4], r1.x); v[5] = __fadd_rn(v[5], r1.y);
            v[6] = __fadd_rn(v[6], r1.z); v[7] = __fadd_rn(v[7], r1.w);
        }
        if (RELU) {
#pragma unroll
            for (int j = 0; j < 8; j++) v[j] = fmaxf(v[j], 0.f);
        }
        if (OUTSLOT >= 0) {
#pragma unroll
            for (int j = 0; j < 8; j++) m = fmaxf(m, v[j]);
        }
        float4 o0 = {v[0], v[1], v[2], v[3]};
        float4 o1 = {v[4], v[5], v[6], v[7]};
        *reinterpret_cast<float4*>(&out[o])     = o0;
        *reinterpret_cast<float4*>(&out[o + 4]) = o1;
    }
    if (OUTSLOT >= 0) blockmax_commit(m, OUTSLOT);
}

// =================================================================
// decoder K=3 conv via Winograd F(4,3), retiled:
// 128 thr, thread = 4co x 4tiles, 96 accum regs, LDS.128 U and V.
// Per-(co,tile) op order identical to R16 -> bit-identical output.
// =================================================================
__global__ void __launch_bounds__(128) k_convwino(
    const float* __restrict__ in, const float* __restrict__ Ug,
    const float* __restrict__ bias, float* __restrict__ out,
    int CO, int CI, int L)
{
    constexpr int LT = 128, COT = 64, CIC = 16;
    __shared__ float s_in[CIC][132];
    __shared__ float s_U[CIC][6][COT];
    __shared__ float s_V[CIC][6][32];

    const int b   = blockIdx.z;
    const int co0 = blockIdx.y * COT;
    const int l0  = blockIdx.x * LT;
    const int tid = threadIdx.x;
    const int tq = tid & 7, cq = tid >> 3;
    const int cs = cq * 4, t0 = tq * 4;

    float M[4][4][6];
#pragma unroll
    for (int i = 0; i < 4; i++)
#pragma unroll
        for (int t = 0; t < 4; t++)
#pragma unroll
            for (int k = 0; k < 6; k++) M[i][t][k] = 0.f;

    for (int ci0 = 0; ci0 < CI; ci0 += CIC) {
        for (int idx = tid; idx < CIC * 130; idx += 128) {
            int ci = idx / 130, x = idx % 130;
            int l = l0 - 1 + x;
            float v = 0.f;
            if (l >= 0 && l < L) v = in[((size_t)b * CI + ci0 + ci) * L + l];
            s_in[ci][x] = v;
        }
        for (int idx = tid; idx < CIC * 6 * COT; idx += 128) {
            int co = idx & 63;
            int k  = (idx >> 6) % 6;
            int ci = idx / 384;
            s_U[ci][k][co] = Ug[((size_t)(ci0 + ci) * 6 + k) * 256 + co0 + co];
        }
        __syncthreads();
        for (int idx = tid; idx < CIC * 32; idx += 128) {
            int ci = idx >> 5, t = idx & 31;
            const float* d = &s_in[ci][4 * t];
            float d0 = d[0], d1 = d[1], d2 = d[2];
            float d3 = d[3], d4 = d[4], d5 = d[5];
            float s1 = d1 + d2, s2 = d3 + d4;
            float q1 = d1 - d2, q2 = d4 - d3;
            float r1 = d3 - d1, r2 = d4 - d2;
            s_V[ci][0][t] = fmaf(4.f, d0, fmaf(-5.f, d2, d4));
            s_V[ci][1][t] = fmaf(-4.f, s1, s2);
            s_V[ci][2][t] = fmaf(4.f, q1, q2);
            s_V[ci][3][t] = fmaf(2.f, r1, r2);
            s_V[ci][4][t] = fmaf(-2.f, r1, r2);
            s_V[ci][5][t] = fmaf(4.f, d1, fmaf(-5.f, d3, d5));
        }
        __syncthreads();
#pragma unroll 2
        for (int ci = 0; ci < CIC; ci++) {
#pragma unroll
            for (int k = 0; k < 6; k++) {
                float4 v4 = *reinterpret_cast<const float4*>(&s_V[ci][k][t0]);
                float4 u4 = *reinterpret_cast<const float4*>(&s_U[ci][k][cs]);
                float vv[4] = {v4.x, v4.y, v4.z, v4.w};
                float uu[4] = {u4.x, u4.y, u4.z, u4.w};
#pragma unroll
                for (int i = 0; i < 4; i++)
#pragma unroll
                    for (int t = 0; t < 4; t++)
                        M[i][t][k] = fmaf(uu[i], vv[t], M[i][t][k]);
            }
        }
        __syncthreads();
    }

#pragma unroll
    for (int i = 0; i < 4; i++) {
        const int co = co0 + cs + i;
        const float bv = bias[co];
        const size_t base = ((size_t)b * CO + co) * L + l0 + t0 * 4;
#pragma unroll
        for (int t = 0; t < 4; t++) {
            float m0 = M[i][t][0], m1 = M[i][t][1], m2 = M[i][t][2];
            float m3 = M[i][t][3], m4 = M[i][t][4], m5 = M[i][t][5];
            float p = m1 + m2, q2 = m1 - m2;
            float r = m3 + m4, s2 = m3 - m4;
            float y0 = (m0 + p) + r;
            float y1 = fmaf(2.f, s2, q2);
            float y2 = fmaf(4.f, r, p);
            float y3 = fmaf(8.f, s2, q2) + m5;
            float4 o0;
            o0.x = fmaxf(y0 + bv, 0.f);
            o0.y = fmaxf(y1 + bv, 0.f);
            o0.z = fmaxf(y2 + bv, 0.f);
            o0.w = fmaxf(y3 + bv, 0.f);
            *reinterpret_cast<float4*>(&out[base + t * 4]) = o0;
        }
    }
}

// =================================================================
// decoder conv1d (fp32 scalar, R13), K=1 path (relu + residual)
// =================================================================
template <int K, bool RELU, bool ADDRES>
__global__ void __launch_bounds__(256) k_conv(
    const float* __restrict__ in, const float* __restrict__ wt,
    const float* __restrict__ bias, const float* __restrict__ res,
    float* __restrict__ out, int CO, int CI, int L)
{
    constexpr int PAD = (K - 1) / 2;
    constexpr int LT = 128, COT = 64, CIC = 16;
    constexpr int LW = LT + 2 * PAD;
    __shared__ float s_in[CIC][LW];
    __shared__ float s_w[CIC][K][COT];

    const int b   = blockIdx.z;
    const int co0 = blockIdx.y * COT;
    const int l0  = blockIdx.x * LT;
    const int tid = threadIdx.x;
    const int lq = tid & 15, cq = tid >> 4;
    const int ls = lq * 8, cs = cq * 4;

    float acc[4][8];
#pragma unroll
    for (int i = 0; i < 4; i++)
#pragma unroll
        for (int j = 0; j < 8; j++) acc[i][j] = 0.f;

    for (int ci0 = 0; ci0 < CI; ci0 += CIC) {
        for (int idx = tid; idx < CIC * LW; idx += 256) {
            int ci = idx / LW, x = idx % LW;
            int l = l0 - PAD + x;
            float v = 0.f;
            if (l >= 0 && l < L) v = in[((size_t)b * CI + ci0 + ci) * L + l];
            s_in[ci][x] = v;
        }
        for (int idx = tid; idx < CIC * K * COT; idx += 256) {
            int co = idx % COT;
            int k  = (idx / COT) % K;
            int ci = idx / (COT * K);
            s_w[ci][k][co] = wt[((size_t)(co0 + co) * CI + ci0 + ci) * K + k];
        }
        __syncthreads();
#pragma unroll 4
        for (int ci = 0; ci < CIC; ci++) {
            float x[8 + K - 1];
#pragma unroll
            for (int t = 0; t < 8 + K - 1; t++) x[t] = s_in[ci][ls + t];
#pragma unroll
            for (int k = 0; k < K; k++) {
                float4 w4 = *reinterpret_cast<const float4*>(&s_w[ci][k][cs]);
                float wv[4] = {w4.x, w4.y, w4.z, w4.w};
#pragma unroll
                for (int i = 0; i < 4; i++)
#pragma unroll
                    for (int j = 0; j < 8; j++)
                        acc[i][j] = fmaf(wv[i], x[j + k], acc[i][j]);
            }
        }
        __syncthreads();
    }
#pragma unroll
    for (int i = 0; i < 4; i++) {
        const int co = co0 + cs + i;
        const float bv = bias[co];
        const size_t o = ((size_t)b * CO + co) * L + l0 + ls;
        float v[8];
#pragma unroll
        for (int j = 0; j < 8; j++) v[j] = __fadd_rn(acc[i][j], bv);
        if (ADDRES) {
            float4 r0 = *reinterpret_cast<const float4*>(&res[o]);
            float4 r1 = *reinterpret_cast<const float4*>(&res[o + 4]);
            v[0] = __fadd_rn(v[0], r0.x); v[1] = __fadd_rn(v[1], r0.y);
            v[2] = __fadd_rn(v[2], r0.z); v[3] = __fadd_rn(v[3], r0.w);
            v[4] = __fadd_rn(v[4], r1.x); v[5] = __fadd_rn(v[5], r1.y);
            v[6] = __fadd_rn(v[6], r1.z); v[7] = __fadd_rn(v[7], r1.w);
        }
        if (RELU) {
#pragma unroll
            for (int j = 0; j < 8; j++) v[j] = fmaxf(v[j], 0.f);
        }
        float4 o0 = {v[0], v[1], v[2], v[3]};
        float4 o1 = {v[4], v[5], v[6], v[7]};
        *reinterpret_cast<float4*>(&out[o])     = o0;
        *reinterpret_cast<float4*>(&out[o + 4]) = o1;
    }
}

// =================================================================
// VQ: single-pass fp32 screen + exact fp64 refine
// =================================================================
__global__ void __launch_bounds__(256) k_vq(
    const float* __restrict__ cb, float* __restrict__ resid,
    float* __restrict__ zq, float* __restrict__ counts,
    float* __restrict__ bsums)
{
    extern __shared__ float sm[];
    float* s_code = sm;
    float* s_cn   = sm + NEMB * LAT;
    const int tid = threadIdx.x;

    for (int idx = tid; idx < NEMB * LAT / 4; idx += 256)
        reinterpret_cast<float4*>(s_code)[idx] =
            reinterpret_cast<const float4*>(cb)[idx];
    __syncthreads();
    for (int e = tid; e < NEMB; e += 256) {
        const float* c = s_code + e * LAT;
        double s = 0.0;
#pragma unroll
        for (int j = 0; j < 64; j++) s = fma((double)c[j], (double)c[j], s);
        s_cn[e] = (float)s;
    }
    __syncthreads();

    const size_t m = (size_t)blockIdx.x * 256 + tid;
    float r[64];
    {
        const float4* g = reinterpret_cast<const float4*>(resid + m * 64);
        float4* rr = reinterpret_cast<float4*>(r);
#pragma unroll
        for (int t = 0; t < 16; t++) rr[t] = g[t];
    }
    double rn64 = 0.0;
#pragma unroll
    for (int j = 0; j < 64; j++) rn64 = fma((double)r[j], (double)r[j], rn64);
    const float rn = (float)rn64;

    float sabs = 0.f;
#pragma unroll
    for (int j = 0; j < 64; j++) sabs = __fadd_rn(sabs, fabsf(r[j]));

    const float margin = 4.8e-7f * rn + 6.4e-8f * sabs + 1e-8f;

    float best_ka = 3.4e38f;
    int   cand[16];
    int   nc = 0;
    bool  overflow = false;
    for (int e = 0; e < NEMB; e += 4) {
        const float4* c0 = reinterpret_cast<const float4*>(s_code + (e + 0) * LAT);
        const float4* c1 = reinterpret_cast<const float4*>(s_code + (e + 1) * LAT);
        const float4* c2 = reinterpret_cast<const float4*>(s_code + (e + 2) * LAT);
        const float4* c3 = reinterpret_cast<const float4*>(s_code + (e + 3) * LAT);
        float d0 = 0.f, d1 = 0.f, d2 = 0.f, d3 = 0.f;
#pragma unroll
        for (int t = 0; t < 16; t++) {
            float4 a0 = c0[t], a1 = c1[t], a2 = c2[t], a3 = c3[t];
            float x0 = r[t*4+0], x1 = r[t*4+1], x2 = r[t*4+2], x3 = r[t*4+3];
            d0 = fmaf(a0.x, x0, d0); d0 = fmaf(a0.y, x1, d0);
            d0 = fmaf(a0.z, x2, d0); d0 = fmaf(a0.w, x3, d0);
            d1 = fmaf(a1.x, x0, d1); d1 = fmaf(a1.y, x1, d1);
            d1 = fmaf(a1.z, x2, d1); d1 = fmaf(a1.w, x3, d1);
            d2 = fmaf(a2.x, x0, d2); d2 = fmaf(a2.y, x1, d2);
            d2 = fmaf(a2.z, x2, d2); d2 = fmaf(a2.w, x3, d2);
            d3 = fmaf(a3.x, x0, d3); d3 = fmaf(a3.y, x1, d3);
            d3 = fmaf(a3.z, x2, d3); d3 = fmaf(a3.w, x3, d3);
        }
        float ka[4];
        ka[0] = __fsub_rn(__fadd_rn(rn, s_cn[e + 0]), __fmul_rn(2.f, d0));
        ka[1] = __fsub_rn(__fadd_rn(rn, s_cn[e + 1]), __fmul_rn(2.f, d1));
        ka[2] = __fsub_rn(__fadd_rn(rn, s_cn[e + 2]), __fmul_rn(2.f, d2));
        ka[3] = __fsub_rn(__fadd_rn(rn, s_cn[e + 3]), __fmul_rn(2.f, d3));
#pragma unroll
        for (int i = 0; i < 4; i++) {
            if (ka[i] < best_ka) best_ka = ka[i];
            if (ka[i] <= best_ka + margin) {
                if (nc < 16) cand[nc++] = e + i;
                else overflow = true;
            }
        }
    }

    float best = 3.4e38f;
    int bi = 0;
    if (!overflow) {
        for (int ci = 0; ci < nc; ci++) {
            int e = cand[ci];
            const float* c = s_code + (size_t)e * LAT;
            double dd = 0.0;
#pragma unroll
            for (int j = 0; j < 64; j++)
                dd = fma((double)c[j], (double)r[j], dd);
            float dot = (float)dd;
            float dist = __fsub_rn(__fadd_rn(rn, s_cn[e]),
                                   __fmul_rn(2.f, dot));
            if (dist < best) { best = dist; bi = e; }
        }
    } else {
        for (int e = 0; e < NEMB; e++) {
            const float* c = s_code + (size_t)e * LAT;
            double dd = 0.0;
#pragma unroll
            for (int j = 0; j < 64; j++)
                dd = fma((double)c[j], (double)r[j], dd);
            float dot = (float)dd;
            float dist = __fsub_rn(__fadd_rn(rn, s_cn[e]),
                                   __fmul_rn(2.f, dot));
            if (dist < best) { best = dist; bi = e; }
        }
    }

    float sq = 0.f;
    {
        const float* c = s_code + bi * LAT;
        float4* rg = reinterpret_cast<float4*>(resid + m * 64);
        float4* zg = reinterpret_cast<float4*>(zq + m * 64);
#pragma unroll
        for (int t = 0; t < 16; t++) {
            float4 zv = zg[t];
            float q[4] = {c[t*4+0], c[t*4+1], c[t*4+2], c[t*4+3]};
            float rv[4] = {r[t*4+0], r[t*4+1], r[t*4+2], r[t*4+3]};
            float4 nr, nz;
            float o_r[4], o_z[4];
#pragma unroll
            for (int u = 0; u < 4; u++) {
                float d  = __fsub_rn(q[u], rv[u]);
                sq = __fadd_rn(sq, __fmul_rn(d, d));
                float qs = __fadd_rn(rv[u], d);
                o_r[u] = __fsub_rn(rv[u], qs);
                o_z[u] = __fadd_rn((&zv.x)[u], qs);
            }
            nr.x = o_r[0]; nr.y = o_r[1]; nr.z = o_r[2]; nr.w = o_r[3];
            nz.x = o_z[0]; nz.y = o_z[1]; nz.z = o_z[2]; nz.w = o_z[3];
            rg[t] = nr; zg[t] = nz;
        }
    }
    atomicAdd(&counts[bi], 1.f);

    __shared__ float red[256];
    red[tid] = sq;
    __syncthreads();
    for (int s = 128; s > 0; s >>= 1) {
        if (tid < s) red[tid] += red[tid + s];
        __syncthreads();
    }
    if (tid == 0) bsums[blockIdx.x] = red[0];
}

__global__ void k_perp(const float* __restrict__ bsums, float* __restrict__ counts,
                       float* __restrict__ scal)
{
    __shared__ float red[512];
    __shared__ float red2[512];
    const int t = threadIdx.x;
    float c = counts[t];
    float avg = c * (1.0f / (float)MROWS);
    red[t] = avg * logf(avg + 1e-10f);
    float s2 = 0.f;
    for (int i = t; i < VQBLOCKS; i += 512) s2 += bsums[i];
    red2[t] = s2;
    __syncthreads();
    for (int s = 256; s > 0; s >>= 1) {
        if (t < s) { red[t] += red[t + s]; red2[t] += red2[t + s]; }
        __syncthreads();
    }
    if (t == 0) {
        scal[1] += expf(-red[0]);
        scal[0] += red2[0];
    }
    counts[t] = 0.f;
}

// =================================================================
// decoder ConvTranspose1d(64->256, K=4, s2, p1) + relu (fp32 scalar)
// =================================================================
__global__ void __launch_bounds__(256) k_dect(
    const float* __restrict__ in, const float* __restrict__ wt,
    const float* __restrict__ bias, float* __restrict__ out)
{
    constexpr int OT = 128, COT = 64, CIC = 32;
    __shared__ float s_in[CIC][66];
    __shared__ float s_w[CIC][4][COT];
    const int b   = blockIdx.z;
    const int co0 = blockIdx.y * COT;
    const int o0  = blockIdx.x * OT;
    const int tid = threadIdx.x;
    const int lq = tid & 15, cq = tid >> 4;
    const int os = lq * 8, cs = cq * 4;
    const int lbase = o0 / 2 - 1;

    float acc[4][8];
#pragma unroll
    for (int i = 0; i < 4; i++)
#pragma unroll
        for (int j = 0; j < 8; j++) acc[i][j] = 0.f;

    for (int ci0 = 0; ci0 < LAT; ci0 += CIC) {
        for (int idx = tid; idx < CIC * 66; idx += 256) {
            int ci = idx / 66, x = idx % 66;
            int l = lbase + x;
            float v = 0.f;
            if (l >= 0 && l < LEN1) v = in[((size_t)b * LAT + ci0 + ci) * LEN1 + l];
            s_in[ci][x] = v;
        }
        for (int idx = tid; idx < CIC * 4 * COT; idx += 256) {
            int co = idx & 63;
            int k  = (idx >> 6) & 3;
            int ci = idx >> 8;
            s_w[ci][k][co] = wt[((size_t)(ci0 + ci) * HID + co0 + co) * 4 + k];
        }
        __syncthreads();
#pragma unroll 4
        for (int ci = 0; ci < CIC; ci++) {
            float x[6];
#pragma unroll
            for (int t = 0; t < 6; t++) x[t] = s_in[ci][(os >> 1) + t];
            float4 W0 = *reinterpret_cast<const float4*>(&s_w[ci][0][cs]);
            float4 W1 = *reinterpret_cast<const float4*>(&s_w[ci][1][cs]);
            float4 W2 = *reinterpret_cast<const float4*>(&s_w[ci][2][cs]);
            float4 W3 = *reinterpret_cast<const float4*>(&s_w[ci][3][cs]);
            float wa[4][4] = {{W0.x, W0.y, W0.z, W0.w},
                              {W1.x, W1.y, W1.z, W1.w},
                              {W2.x, W2.y, W2.z, W2.w},
                              {W3.x, W3.y, W3.z, W3.w}};
#pragma unroll
            for (int jj = 0; jj < 4; jj++) {
                float xe0 = x[jj], xe1 = x[jj + 1], xo2 = x[jj + 2];
#pragma unroll
                for (int i = 0; i < 4; i++) {
                    acc[i][2 * jj]     = fmaf(wa[1][i], xe1, fmaf(wa[3][i], xe0, acc[i][2 * jj]));
                    acc[i][2 * jj + 1] = fmaf(wa[0][i], xo2, fmaf(wa[2][i], xe1, acc[i][2 * jj + 1]));
                }
            }
        }
        __syncthreads();
    }
#pragma unroll
    for (int i = 0; i < 4; i++) {
        const int co = co0 + cs + i;
        const float bv = bias[co];
        const size_t o = ((size_t)b * HID + co) * LEN2 + o0 + os;
        float v[8];
#pragma unroll
        for (int j = 0; j < 8; j++) v[j] = fmaxf(__fadd_rn(acc[i][j], bv), 0.f);
        float4 q0 = {v[0], v[1], v[2], v[3]};
        float4 q1 = {v[4], v[5], v[6], v[7]};
        *reinterpret_cast<float4*>(&out[o])     = q0;
        *reinterpret_cast<float4*>(&out[o + 4]) = q1;
    }
}

// =================================================================
// decoder ConvTranspose1d(256->1, K=3, s1, p1) (fp32)
// =================================================================
__global__ void __launch_bounds__(256) k_decfinal(
    const float* __restrict__ in, const float* __restrict__ wt,
    const float* __restrict__ bias, float* __restrict__ out)
{
    __shared__ float s_w[HID * 3];
    __shared__ float s_in[32][258];
    const int b  = blockIdx.y;
    const int o0 = blockIdx.x * 256;
    const int tx = threadIdx.x;
    for (int i = tx; i < HID * 3; i += 256) s_w[i] = wt[i];
    float acc = 0.f;
    for (int cc = 0; cc < HID; cc += 32) {
        __syncthreads();
        for (int idx = tx; idx < 32 * 258; idx += 256) {
            int ci = idx / 258, x = idx % 258;
            int l = o0 - 1 + x;
            s_in[ci][x] = (l >= 0 && l < LEN2)
                        ? in[((size_t)b * HID + cc + ci) * LEN2 + l] : 0.f;
        }
        __syncthreads();
#pragma unroll 8
        for (int ci = 0; ci < 32; ci++) {
            acc = fmaf(s_w[(cc + ci) * 3 + 0], s_in[ci][tx + 2], acc);
            acc = fmaf(s_w[(cc + ci) * 3 + 1], s_in[ci][tx + 1], acc);
            acc = fmaf(s_w[(cc + ci) * 3 + 2], s_in[ci][tx + 0], acc);
        }
    }
    out[(size_t)b * LEN2 + o0 + tx] = __fadd_rn(acc, bias[0]);
}

// =================================================================
// out projection (fp32 scalar)
// =================================================================
__global__ void __launch_bounds__(256) k_outproj(
    const float* __restrict__ dv, const float* __restrict__ W,
    const float* __restrict__ bias, float* __restrict__ out)
{
    constexpr int KC = 32;
    __shared__ float s_d[KC][136];
    __shared__ float s_w[KC][68];
    const int j0  = blockIdx.x * 64;
    const int tid = threadIdx.x;
    const int bq = tid & 15, jq = tid >> 4;
    const int bs = bq * 8, js = jq * 4;
    float acc[8][4];
#pragma unroll
    for (int i = 0; i < 8; i++)
#pragma unroll
        for (int j = 0; j < 4; j++) acc[i][j] = 0.f;

    for (int k0 = 0; k0 < NITEMS; k0 += KC) {
        for (int idx = tid; idx < KC * 128; idx += 256) {
            int bb = idx >> 5, k = idx & 31;
            s_d[k][bb] = dv[(size_t)bb * NITEMS + k0 + k];
        }
        for (int idx = tid; idx < KC * 64; idx += 256) {
            int j = idx >> 5, k = idx & 31;
            s_w[k][j] = W[(size_t)(j0 + j) * NITEMS + k0 + k];
        }
        __syncthreads();
#pragma unroll
        for (int k = 0; k < KC; k++) {
            float4 w4 = *reinterpret_cast<const float4*>(&s_w[k][js]);
            float xb[8];
            *reinterpret_cast<float4*>(&xb[0]) = *reinterpret_cast<const float4*>(&s_d[k][bs]);
            *reinterpret_cast<float4*>(&xb[4]) = *reinterpret_cast<const float4*>(&s_d[k][bs + 4]);
            float wv[4] = {w4.x, w4.y, w4.z, w4.w};
#pragma unroll
            for (int i = 0; i < 8; i++)
#pragma unroll
                for (int j = 0; j < 4; j++)
                    acc[i][j] = fmaf(xb[i], wv[j], acc[i][j]);
        }
        __syncthreads();
    }
#pragma unroll
    for (int i = 0; i < 8; i++) {
#pragma unroll
        for (int j = 0; j < 4; j++)
            out[(size_t)(bs + i) * NITEMS + j0 + js + j] =
                __fadd_rn(acc[i][j], bias[j0 + js + j]);
    }
}

__global__ void k_final(const float* __restrict__ scal, float* __restrict__ out, int out_size)
{
    if (out_size >= BATCH * NITEMS + 2) {
        out[BATCH * NITEMS + 0] = 1.25f * scal[0] * (1.0f / 33554432.0f);
        out[BATCH * NITEMS + 1] = scal[1] * 0.25f;
    }
}

// =================================================================
extern "C" void kernel_launch(void* const* d_in, const int* in_sizes, int n_in,
                              void* d_out, int out_size)
{
    const int*   uid  = (const int*)  d_in[0];
    const float* mat  = (const float*)d_in[1];
    const float* ecw  = (const float*)d_in[2];
    const float* ecb  = (const float*)d_in[3];
    const float* erw1 = (const float*)d_in[4];
    const float* erb1 = (const float*)d_in[5];
    const float* erw2 = (const float*)d_in[6];
    const float* erb2 = (const float*)d_in[7];
    const float* efw  = (const float*)d_in[8];
    const float* efb  = (const float*)d_in[9];
    const float* cbs  = (const float*)d_in[10];
    const float* dtw  = (const float*)d_in[11];
    const float* dtb  = (const float*)d_in[12];
    const float* drw1 = (const float*)d_in[13];
    const float* drb1 = (const float*)d_in[14];
    const float* drw2 = (const float*)d_in[15];
    const float* drb2 = (const float*)d_in[16];
    const float* dfw  = (const float*)d_in[17];
    const float* dfb  = (const float*)d_in[18];
    const float* opw  = (const float*)d_in[19];
    const float* opb  = (const float*)d_in[20];
    float* out = (float*)d_out;

    float *bufA, *bufB, *resid, *zq, *dvec, *counts, *scal, *bsums, *Uw;
    unsigned int* xmax;
    cudaGetSymbolAddress((void**)&bufA,   g_bufA);
    cudaGetSymbolAddress((void**)&bufB,   g_bufB);
    cudaGetSymbolAddress((void**)&resid,  g_res);
    cudaGetSymbolAddress((void**)&zq,     g_zq);
    cudaGetSymbolAddress((void**)&dvec,   g_dvec);
    cudaGetSymbolAddress((void**)&counts, g_counts);
    cudaGetSymbolAddress((void**)&scal,   g_scal);
    cudaGetSymbolAddress((void**)&bsums,  g_bsums);
    cudaGetSymbolAddress((void**)&xmax,   g_xmax);
    cudaGetSymbolAddress((void**)&Uw,     g_Uw);

    const int vq_smem = (NEMB * LAT + NEMB) * (int)sizeof(float);
    cudaFuncSetAttribute(k_vq, cudaFuncAttributeMaxDynamicSharedMemorySize, vq_smem);

    cudaMemsetAsync(zq, 0, (size_t)33554432 * sizeof(float), 0);
    cudaMemsetAsync(scal, 0, 2 * sizeof(float), 0);
    cudaMemsetAsync(counts, 0, NEMB * sizeof(float), 0);
    cudaMemsetAsync(xmax, 0, 8 * sizeof(unsigned int), 0);

    // ---------------- encoder (grid-accumulator exact, fused max) -------
    k_enc_conv1<<<dim3(LEN1 / 128, BATCH), 128>>>(uid, mat, ecw, ecb, bufA);

    k_makeC<<<1, 256>>>(erw1, HID, HID * 3, 0);
    k_convgrid<3, true, false, 1><<<dim3(LEN1 / 128, HID / 64, BATCH), 256>>>(
        bufA, erw1, erb1, nullptr, bufB, HID, HID, LEN1, 0);

    k_makeC<<<1, 256>>>(erw2, HID, HID * 1, 1);
    k_convgrid<1, true, true, 2><<<dim3(LEN1 / 128, HID / 64, BATCH), 256>>>(
        bufB, erw2, erb2, bufA, bufA, HID, HID, LEN1, 1);

    k_makeC<<<1, 256>>>(erw1 + (size_t)HID * HID * 3, HID, HID * 3, 2);
    k_convgrid<3, true, false, 3><<<dim3(LEN1 / 128, HID / 64, BATCH), 256>>>(
        bufA, erw1 + (size_t)HID * HID * 3, erb1 + HID, nullptr, bufB,
        HID, HID, LEN1, 2);

    k_makeC<<<1, 256>>>(erw2 + (size_t)HID * HID, HID, HID * 1, 3);
    k_convgrid<1, true, true, 4><<<dim3(LEN1 / 128, HID / 64, BATCH), 256>>>(
        bufB, erw2 + (size_t)HID * HID, erb2 + HID, bufA, bufA,
        HID, HID, LEN1, 3);

    k_makeC<<<1, 256>>>(efw, LAT, HID * 3, 4);
    k_convgrid<3, false, false, -1><<<dim3(LEN1 / 128, LAT / 64, BATCH), 256>>>(
        bufA, efw, efb, nullptr, resid, LAT, HID, LEN1, 4);

    // ---------------- residual VQ ----------------
    for (int q = 0; q < NQ; q++) {
        k_vq<<<VQBLOCKS, 256, vq_smem>>>(cbs + (size_t)q * NEMB * LAT,
                                         resid, zq, counts, bsums);
        k_perp<<<1, 512>>>(bsums, counts, scal);
    }

    // ---------------- decoder (retiled Winograd K=3, scalar K=1) --------
    k_dect<<<dim3(LEN2 / 128, HID / 64, BATCH), 256>>>(zq, dtw, dtb, bufA);
    for (int i = 0; i < 2; i++) {
        k_wtrans<<<256, 256>>>(drw1 + (size_t)i * HID * HID * 3, Uw, HID);
        k_convwino<<<dim3(LEN2 / 128, HID / 64, BATCH), 128>>>(
            bufA, Uw, drb1 + i * HID, bufB, HID, HID, LEN2);
        k_conv<1, true, true><<<dim3(LEN2 / 128, HID / 64, BATCH), 256>>>(
            bufB, drw2 + (size_t)i * HID * HID, drb2 + i * HID, bufA, bufA,
            HID, HID, LEN2);
    }
    k_decfinal<<<dim3(LEN2 / 256, BATCH), 256>>>(bufA, dfw, dfb, dvec);

    // ---------------- output projection + scalars ----------------
    k_outproj<<<NITEMS / 64, 256>>>(dvec, opw, opb, out);
    k_final<<<1, 1>>>(scal, out, out_size);
}